// round 2
// baseline (speedup 1.0000x reference)
#include <cuda_runtime.h>
#include <math.h>

#define N0   120000
#define N1V  12000
#define N2V  1024
#define E1N  300000
#define E2N  10240
#define F_IN 602
#define H1N  8
#define C1N  8
#define D1   64      // H1*C1
#define NCLS 41
#define NEG  0.2f

#define EL1  (E1N + N1V)   // edges + self loops, layer 1 = 312000
#define EL2  (E2N + N2V)   // layer 2 = 11264

// ---------------- scratch (static device globals; no allocation) ----------------
__device__ float    g_Hfull[(size_t)N0 * D1];   // x @ W1           (~29.3 MB)
__device__ float    g_as1[N0 * H1N];
__device__ float    g_ad1[N1V * H1N];
__device__ unsigned g_m1[N1V * H1N];
__device__ float    g_s1[N1V * H1N];
__device__ float    g_out1[N1V * D1];           // aggregated, then (+b1, ELU) in place
__device__ float    g_H2[N1V * NCLS];           // h1 @ W2
__device__ float    g_as2[N1V];
__device__ float    g_ad2[N2V];
__device__ unsigned g_m2[N2V];
__device__ float    g_s2[N2V];
__device__ float    g_out2[N2V * NCLS];
__device__ int      g_e64;                      // 1 if edge indices are int64

// order-preserving float <-> uint for atomicMax
__device__ __forceinline__ unsigned fenc(float f) {
    unsigned u = __float_as_uint(f);
    return (u & 0x80000000u) ? ~u : (u | 0x80000000u);
}
__device__ __forceinline__ float fdec(unsigned u) {
    return __uint_as_float((u & 0x80000000u) ? (u & 0x7fffffffu) : ~u);
}

__device__ __forceinline__ int eidx(const void* p, long long pos) {
    return g_e64 ? (int)((const long long*)p)[pos] : ((const int*)p)[pos];
}

// ---------------- dtype sniff: int64 edge values are all < N0 ----------------
__global__ void k_detect(const void* e1p) {
    if (threadIdx.x == 0 && blockIdx.x == 0) {
        const long long* p = (const long long*)e1p;
        bool ok = true;
        for (int i = 0; i < 16; i++) {
            long long v = p[i];
            if (v < 0 || v >= (long long)N0) { ok = false; break; }
        }
        g_e64 = ok ? 1 : 0;
    }
}

// ---------------- init accumulators each replay ----------------
__global__ void k_init() {
    int nt = gridDim.x * blockDim.x;
    int t0 = blockIdx.x * blockDim.x + threadIdx.x;
    for (int i = t0; i < N1V * D1; i += nt) g_out1[i] = 0.f;
    for (int i = t0; i < N1V * H1N; i += nt) { g_s1[i] = 0.f; g_m1[i] = 0u; }
    for (int i = t0; i < N2V * NCLS; i += nt) g_out2[i] = 0.f;
    for (int i = t0; i < N2V; i += nt) { g_s2[i] = 0.f; g_m2[i] = 0u; }
}

// ---------------- GEMM1: Hfull[N0,64] = x[N0,602] @ W1[602,64] (no bias) -----
#define BM 64
#define BN 64
#define BK 16
__global__ void __launch_bounds__(256) k_gemm1(const float* __restrict__ x,
                                               const float* __restrict__ W) {
    __shared__ float As[BK][BM + 4];
    __shared__ float Bs[BK][BN];
    int row0 = blockIdx.x * BM;
    int t = threadIdx.x;
    int tx = t & 15, ty = t >> 4;
    float acc[4][4] = {};

    for (int k0 = 0; k0 < F_IN; k0 += BK) {
#pragma unroll
        for (int i = 0; i < 4; i++) {
            int e = t + 256 * i;
            int m = e >> 4, k = e & 15;
            int kk = k0 + k;
            As[k][m] = (kk < F_IN) ? x[(size_t)(row0 + m) * F_IN + kk] : 0.f;
        }
#pragma unroll
        for (int i = 0; i < 4; i++) {
            int e = t + 256 * i;
            int k = e >> 6, n = e & 63;
            int kk = k0 + k;
            Bs[k][n] = (kk < F_IN) ? W[(size_t)kk * BN + n] : 0.f;
        }
        __syncthreads();
#pragma unroll
        for (int k = 0; k < BK; k++) {
            float a[4], b[4];
#pragma unroll
            for (int i = 0; i < 4; i++) a[i] = As[k][ty * 4 + i];
#pragma unroll
            for (int j = 0; j < 4; j++) b[j] = Bs[k][tx * 4 + j];
#pragma unroll
            for (int i = 0; i < 4; i++)
#pragma unroll
                for (int j = 0; j < 4; j++) acc[i][j] = fmaf(a[i], b[j], acc[i][j]);
        }
        __syncthreads();
    }
#pragma unroll
    for (int i = 0; i < 4; i++)
#pragma unroll
        for (int j = 0; j < 4; j++)
            g_Hfull[(size_t)(row0 + ty * 4 + i) * D1 + tx * 4 + j] = acc[i][j];
}

// ---------------- per-node attention logits, layer 1 ----------------
__global__ void k_att1(const float* __restrict__ a_src, const float* __restrict__ a_dst) {
    int t = blockIdx.x * blockDim.x + threadIdx.x;
    if (t >= N0 * H1N) return;
    int node = t >> 3, h = t & 7;
    const float* hp = g_Hfull + (size_t)node * D1 + h * C1N;
    float as = 0.f;
#pragma unroll
    for (int c = 0; c < C1N; c++) as += hp[c] * a_src[h * C1N + c];
    g_as1[t] = as;
    if (node < N1V) {
        float ad = 0.f;
#pragma unroll
        for (int c = 0; c < C1N; c++) ad += hp[c] * a_dst[h * C1N + c];
        g_ad1[node * H1N + h] = ad;
    }
}

__device__ __forceinline__ void edge1_sd(const void* e1p, int e, int& s, int& d) {
    if (e < E1N) { s = eidx(e1p, e); d = eidx(e1p, (long long)E1N + e); }
    else { s = d = e - E1N; }
}

__global__ void k_edge1_max(const void* e1p) {
    int t = blockIdx.x * blockDim.x + threadIdx.x;
    if (t >= EL1 * H1N) return;
    int e = t >> 3, h = t & 7;
    int s, d; edge1_sd(e1p, e, s, d);
    float al = g_as1[s * H1N + h] + g_ad1[d * H1N + h];
    al = al > 0.f ? al : NEG * al;
    atomicMax(&g_m1[d * H1N + h], fenc(al));
}

__global__ void k_edge1_sum(const void* e1p) {
    int t = blockIdx.x * blockDim.x + threadIdx.x;
    if (t >= EL1 * H1N) return;
    int e = t >> 3, h = t & 7;
    int s, d; edge1_sd(e1p, e, s, d);
    float al = g_as1[s * H1N + h] + g_ad1[d * H1N + h];
    al = al > 0.f ? al : NEG * al;
    int dh = d * H1N + h;
    atomicAdd(&g_s1[dh], expf(al - fdec(g_m1[dh])));
}

__global__ void k_edge1_agg(const void* e1p) {
    int t = blockIdx.x * blockDim.x + threadIdx.x;
    if (t >= EL1 * H1N) return;
    int e = t >> 3, h = t & 7;
    int s, d; edge1_sd(e1p, e, s, d);
    int dh = d * H1N + h;
    float al = g_as1[s * H1N + h] + g_ad1[dh];
    al = al > 0.f ? al : NEG * al;
    float w = expf(al - fdec(g_m1[dh])) / (g_s1[dh] + 1e-16f);
    const float* hs = g_Hfull + (size_t)s * D1 + h * C1N;
    float* o = g_out1 + d * D1 + h * C1N;
#pragma unroll
    for (int c = 0; c < C1N; c++) atomicAdd(&o[c], hs[c] * w);
}

// ---------------- +b1 then ELU, in place ----------------
__global__ void k_elu(const float* __restrict__ b1) {
    int i = blockIdx.x * blockDim.x + threadIdx.x;
    if (i >= N1V * D1) return;
    float v = g_out1[i] + b1[i & (D1 - 1)];
    g_out1[i] = v > 0.f ? v : expm1f(v);
}

// ---------------- GEMM2: H2[N1,41] = h1[N1,64] @ W2[64,41] (no bias) --------
__global__ void k_gemm2(const float* __restrict__ W2) {
    __shared__ float Ws[D1 * NCLS];
    for (int i = threadIdx.x; i < D1 * NCLS; i += blockDim.x) Ws[i] = W2[i];
    __syncthreads();
    int t = blockIdx.x * blockDim.x + threadIdx.x;
    if (t >= N1V * NCLS) return;
    int row = t / NCLS, col = t - row * NCLS;
    const float* hr = g_out1 + row * D1;
    float acc = 0.f;
#pragma unroll
    for (int k = 0; k < D1; k++) acc = fmaf(hr[k], Ws[k * NCLS + col], acc);
    g_H2[t] = acc;
}

__global__ void k_att2(const float* __restrict__ a_src, const float* __restrict__ a_dst) {
    int i = blockIdx.x * blockDim.x + threadIdx.x;
    if (i >= N1V) return;
    const float* hp = g_H2 + i * NCLS;
    float as = 0.f;
#pragma unroll
    for (int c = 0; c < NCLS; c++) as += hp[c] * a_src[c];
    g_as2[i] = as;
    if (i < N2V) {
        float ad = 0.f;
#pragma unroll
        for (int c = 0; c < NCLS; c++) ad += hp[c] * a_dst[c];
        g_ad2[i] = ad;
    }
}

__device__ __forceinline__ void edge2_sd(const void* e2p, int e, int& s, int& d) {
    if (e < E2N) { s = eidx(e2p, e); d = eidx(e2p, (long long)E2N + e); }
    else { s = d = e - E2N; }
}

__global__ void k_edge2_max(const void* e2p) {
    int e = blockIdx.x * blockDim.x + threadIdx.x;
    if (e >= EL2) return;
    int s, d; edge2_sd(e2p, e, s, d);
    float al = g_as2[s] + g_ad2[d];
    al = al > 0.f ? al : NEG * al;
    atomicMax(&g_m2[d], fenc(al));
}

__global__ void k_edge2_sum(const void* e2p) {
    int e = blockIdx.x * blockDim.x + threadIdx.x;
    if (e >= EL2) return;
    int s, d; edge2_sd(e2p, e, s, d);
    float al = g_as2[s] + g_ad2[d];
    al = al > 0.f ? al : NEG * al;
    atomicAdd(&g_s2[d], expf(al - fdec(g_m2[d])));
}

__global__ void k_edge2_agg(const void* e2p) {
    int t = blockIdx.x * blockDim.x + threadIdx.x;
    if (t >= EL2 * NCLS) return;
    int e = t / NCLS, c = t - e * NCLS;
    int s, d; edge2_sd(e2p, e, s, d);
    float al = g_as2[s] + g_ad2[d];
    al = al > 0.f ? al : NEG * al;
    float w = expf(al - fdec(g_m2[d])) / (g_s2[d] + 1e-16f);
    atomicAdd(&g_out2[d * NCLS + c], g_H2[s * NCLS + c] * w);
}

// ---------------- final: +b2, row log_softmax, write d_out ----------------
__global__ void k_final(float* __restrict__ out, const float* __restrict__ b2) {
    int d = blockIdx.x;
    int lane = threadIdx.x;
    float v0 = (lane < NCLS) ? g_out2[d * NCLS + lane] + b2[lane] : -INFINITY;
    float v1 = (lane + 32 < NCLS) ? g_out2[d * NCLS + lane + 32] + b2[lane + 32] : -INFINITY;
    float m = fmaxf(v0, v1);
#pragma unroll
    for (int o = 16; o > 0; o >>= 1) m = fmaxf(m, __shfl_xor_sync(0xffffffffu, m, o));
    float s = ((lane < NCLS) ? expf(v0 - m) : 0.f) + ((lane + 32 < NCLS) ? expf(v1 - m) : 0.f);
#pragma unroll
    for (int o = 16; o > 0; o >>= 1) s += __shfl_xor_sync(0xffffffffu, s, o);
    float ls = m + logf(s);
    if (lane < NCLS) out[d * NCLS + lane] = v0 - ls;
    if (lane + 32 < NCLS) out[d * NCLS + lane + 32] = v1 - ls;
}

// ---------------- launch ----------------
extern "C" void kernel_launch(void* const* d_in, const int* in_sizes, int n_in,
                              void* d_out, int out_size) {
    const float* x = nullptr;
    const void* e1 = nullptr;
    const void* e2 = nullptr;
    const float *W1 = nullptr, *as1 = nullptr, *ad1 = nullptr, *b1 = nullptr;
    const float *W2 = nullptr, *as2 = nullptr, *ad2 = nullptr, *b2 = nullptr;

    for (int i = 0; i < n_in; i++) {
        switch (in_sizes[i]) {
            case N0 * F_IN:   x  = (const float*)d_in[i]; break;  // 72,240,000
            case 2 * E1N:     e1 = d_in[i]; break;                // 600,000
            case 2 * E2N:     e2 = d_in[i]; break;                // 20,480
            case F_IN * D1:                                       // 38,528
                W1  = (const float*)d_in[i];
                if (i + 3 < n_in) {
                    as1 = (const float*)d_in[i + 1];
                    ad1 = (const float*)d_in[i + 2];
                    b1  = (const float*)d_in[i + 3];
                }
                break;
            case D1 * NCLS:                                       // 2,624
                W2  = (const float*)d_in[i];
                if (i + 3 < n_in) {
                    as2 = (const float*)d_in[i + 1];
                    ad2 = (const float*)d_in[i + 2];
                    b2  = (const float*)d_in[i + 3];
                }
                break;
            default: break;
        }
    }

    float* out = (float*)d_out;
    const int TPB = 256;

    k_detect<<<1, 32>>>(e1);
    k_init<<<3000, TPB>>>();
    k_gemm1<<<N0 / BM, TPB>>>(x, W1);
    k_att1<<<(N0 * H1N + TPB - 1) / TPB, TPB>>>(as1, ad1);
    k_edge1_max<<<(EL1 * H1N + TPB - 1) / TPB, TPB>>>(e1);
    k_edge1_sum<<<(EL1 * H1N + TPB - 1) / TPB, TPB>>>(e1);
    k_edge1_agg<<<(EL1 * H1N + TPB - 1) / TPB, TPB>>>(e1);
    k_elu<<<(N1V * D1 + TPB - 1) / TPB, TPB>>>(b1);
    k_gemm2<<<(N1V * NCLS + TPB - 1) / TPB, TPB>>>(W2);
    k_att2<<<(N1V + TPB - 1) / TPB, TPB>>>(as2, ad2);
    k_edge2_max<<<(EL2 + TPB - 1) / TPB, TPB>>>(e2);
    k_edge2_sum<<<(EL2 + TPB - 1) / TPB, TPB>>>(e2);
    k_edge2_agg<<<(EL2 * NCLS + TPB - 1) / TPB, TPB>>>(e2);
    k_final<<<N2V, 32>>>(out, b2);
}

// round 4
// speedup vs baseline: 1.7538x; 1.7538x over previous
#include <cuda_runtime.h>
#include <cuda_bf16.h>
#include <math.h>

#define N0   120000
#define N1V  12000
#define N2V  1024
#define E1N  300000
#define E2N  10240
#define F_IN 602
#define H1N  8
#define C1N  8
#define D1   64      // H1*C1
#define NCLS 41
#define NEG  0.2f

#define EL1  (E1N + N1V)   // 312000
#define EL2  (E2N + N2V)   // 11264

// ---------------- scratch (static device globals; no allocation) ----------------
__device__ float    g_Hfull[(size_t)N0 * D1];   // x @ W1 (~29.3 MB)
__device__ float    g_as1[N0 * H1N];
__device__ float    g_ad1[N1V * H1N];
__device__ float    g_s1[N1V * H1N];
__device__ float    g_ex1[(size_t)EL1 * H1N];   // cached exp(alpha) per edge-head (~10MB)
__device__ float    g_out1[N1V * D1];
__device__ float    g_H2[N1V * NCLS];
__device__ float    g_as2[N1V];
__device__ float    g_ad2[N2V];
__device__ float    g_s2[N2V];
__device__ float    g_out2[N2V * NCLS];
__device__ int      g_e64;

__device__ __forceinline__ int eidx(const void* p, long long pos) {
    return g_e64 ? (int)((const long long*)p)[pos] : ((const int*)p)[pos];
}

__global__ void k_detect(const void* e1p) {
    if (threadIdx.x == 0 && blockIdx.x == 0) {
        const long long* p = (const long long*)e1p;
        bool ok = true;
        for (int i = 0; i < 16; i++) {
            long long v = p[i];
            if (v < 0 || v >= (long long)N0) { ok = false; break; }
        }
        g_e64 = ok ? 1 : 0;
    }
}

__global__ void k_init() {
    int nt = gridDim.x * blockDim.x;
    int t0 = blockIdx.x * blockDim.x + threadIdx.x;
    for (int i = t0; i < N1V * D1; i += nt) g_out1[i] = 0.f;
    for (int i = t0; i < N1V * H1N; i += nt) g_s1[i] = 0.f;
    for (int i = t0; i < N2V * NCLS; i += nt) g_out2[i] = 0.f;
    for (int i = t0; i < N2V; i += nt) g_s2[i] = 0.f;
}

// ======================= GEMM1 via mma.sync bf16 (bf16x3 split) =======================
// H[120000,64] = x[120000,602] @ W1[602,64].
// CTA tile M=128, N=64; 8 warps (4 M x 2 N), warp tile 32x32.
// K chunks of 32 fp32 (19 chunks, zero-padded to 608), double-buffered smem.
#define KC      32
#define NCHUNK  19
#define SA      17              // u32 stride for A rows (KC/2 + 1)
#define SB      17
#define BUFB    26112           // bytes per buffer
#define OFF_AH  0               // 128*17*4 = 8704
#define OFF_AL  8704
#define OFF_BH  17408           // 64*17*4 = 4352
#define OFF_BL  21760
#define SMEM_G1 (2 * BUFB)      // 52224
#define CS_STRIDE 72            // float stride for C staging

__device__ __forceinline__ void cvt2(float2 v, unsigned& hp, unsigned& lp) {
    __nv_bfloat16 hx = __float2bfloat16(v.x), hy = __float2bfloat16(v.y);
    float rx = v.x - __bfloat162float(hx), ry = v.y - __bfloat162float(hy);
    __nv_bfloat16 lx = __float2bfloat16(rx), ly = __float2bfloat16(ry);
    hp = ((unsigned)__bfloat16_as_ushort(hy) << 16) | __bfloat16_as_ushort(hx);
    lp = ((unsigned)__bfloat16_as_ushort(ly) << 16) | __bfloat16_as_ushort(lx);
}

__device__ __forceinline__ void mma_bf16(float& c0, float& c1, float& c2, float& c3,
                                         unsigned a0, unsigned a1, unsigned a2, unsigned a3,
                                         unsigned b0, unsigned b1) {
    asm volatile(
        "mma.sync.aligned.m16n8k16.row.col.f32.bf16.bf16.f32 "
        "{%0,%1,%2,%3}, {%4,%5,%6,%7}, {%8,%9}, {%0,%1,%2,%3};"
        : "+f"(c0), "+f"(c1), "+f"(c2), "+f"(c3)
        : "r"(a0), "r"(a1), "r"(a2), "r"(a3), "r"(b0), "r"(b1));
}

__global__ void __launch_bounds__(256, 2)
k_gemm1_mma(const float* __restrict__ x, const float* __restrict__ W1,
            const float* __restrict__ a_src, const float* __restrict__ a_dst) {
    extern __shared__ unsigned char smem[];
    int t = threadIdx.x;
    int w = t >> 5, lane = t & 31;
    int g = lane >> 2, tig = lane & 3;
    int wm = w & 3, wn = w >> 2;
    int row0 = blockIdx.x * 128;

    float acc[2][4][4];
#pragma unroll
    for (int mi = 0; mi < 2; mi++)
#pragma unroll
        for (int ni = 0; ni < 4; ni++)
#pragma unroll
            for (int q = 0; q < 4; q++) acc[mi][ni][q] = 0.f;

    // -------- prologue: load chunk 0 directly into buffer 0 --------
    {
        unsigned* Ah = (unsigned*)(smem + OFF_AH);
        unsigned* Al = (unsigned*)(smem + OFF_AL);
        unsigned* Bh = (unsigned*)(smem + OFF_BH);
        unsigned* Bl = (unsigned*)(smem + OFF_BL);
#pragma unroll
        for (int j = 0; j < 8; j++) {
            int idx = t + 256 * j;
            int row = idx >> 4, kq = idx & 15;
            int gk = 2 * kq;                      // chunk 0: k0 = 0
            float2 v = make_float2(0.f, 0.f);
            if (row0 + row < N0)
                v = *(const float2*)(x + (size_t)(row0 + row) * F_IN + gk);
            unsigned hp, lp; cvt2(v, hp, lp);
            Ah[row * SA + kq] = hp; Al[row * SA + kq] = lp;
        }
#pragma unroll
        for (int j = 0; j < 4; j++) {
            int idx = t + 256 * j;
            int n = idx & 63, a = idx >> 6;
            float v0 = W1[(size_t)(2 * a) * D1 + n];
            float v1 = W1[(size_t)(2 * a + 1) * D1 + n];
            unsigned hp, lp; cvt2(make_float2(v0, v1), hp, lp);
            Bh[n * SB + a] = hp; Bl[n * SB + a] = lp;
        }
    }
    __syncthreads();

    for (int c = 0; c < NCHUNK; c++) {
        int cur = c & 1;
        // -------- prefetch next chunk into registers --------
        float2 av[8];
        float bv0[4], bv1[4];
        int arow[8], akq[8], bn[4], ba[4];
        bool have_next = (c + 1 < NCHUNK);
        if (have_next) {
            int k0 = (c + 1) * KC;
#pragma unroll
            for (int j = 0; j < 8; j++) {
                int idx = t + 256 * j;
                int row = idx >> 4, kq = idx & 15;
                int gk = k0 + 2 * kq;
                arow[j] = row; akq[j] = kq;
                float2 v = make_float2(0.f, 0.f);
                if (row0 + row < N0 && gk < F_IN)
                    v = *(const float2*)(x + (size_t)(row0 + row) * F_IN + gk);
                av[j] = v;
            }
#pragma unroll
            for (int j = 0; j < 4; j++) {
                int idx = t + 256 * j;
                int n = idx & 63, a = idx >> 6;
                bn[j] = n; ba[j] = a;
                int k = k0 + 2 * a;
                bv0[j] = (k < F_IN) ? W1[(size_t)k * D1 + n] : 0.f;
                bv1[j] = (k + 1 < F_IN) ? W1[(size_t)(k + 1) * D1 + n] : 0.f;
            }
        }
        // -------- compute on current buffer --------
        {
            const unsigned* Ah = (const unsigned*)(smem + cur * BUFB + OFF_AH);
            const unsigned* Al = (const unsigned*)(smem + cur * BUFB + OFF_AL);
            const unsigned* Bh = (const unsigned*)(smem + cur * BUFB + OFF_BH);
            const unsigned* Bl = (const unsigned*)(smem + cur * BUFB + OFF_BL);
#pragma unroll
            for (int s = 0; s < 2; s++) {
                int kb = s * 8;
                unsigned ah[2][4], ax[2][4], bx[4][2];
#pragma unroll
                for (int mi = 0; mi < 2; mi++) {
                    int r0 = wm * 32 + mi * 16 + g;
                    ah[mi][0] = Ah[r0 * SA + kb + tig];
                    ah[mi][1] = Ah[(r0 + 8) * SA + kb + tig];
                    ah[mi][2] = Ah[r0 * SA + kb + tig + 4];
                    ah[mi][3] = Ah[(r0 + 8) * SA + kb + tig + 4];
                }
#pragma unroll
                for (int ni = 0; ni < 4; ni++) {
                    int n = wn * 32 + ni * 8 + g;
                    bx[ni][0] = Bh[n * SB + kb + tig];
                    bx[ni][1] = Bh[n * SB + kb + tig + 4];
                }
#pragma unroll
                for (int mi = 0; mi < 2; mi++)
#pragma unroll
                    for (int ni = 0; ni < 4; ni++)
                        mma_bf16(acc[mi][ni][0], acc[mi][ni][1], acc[mi][ni][2], acc[mi][ni][3],
                                 ah[mi][0], ah[mi][1], ah[mi][2], ah[mi][3],
                                 bx[ni][0], bx[ni][1]);
                // A_lo x B_hi
#pragma unroll
                for (int mi = 0; mi < 2; mi++) {
                    int r0 = wm * 32 + mi * 16 + g;
                    ax[mi][0] = Al[r0 * SA + kb + tig];
                    ax[mi][1] = Al[(r0 + 8) * SA + kb + tig];
                    ax[mi][2] = Al[r0 * SA + kb + tig + 4];
                    ax[mi][3] = Al[(r0 + 8) * SA + kb + tig + 4];
                }
#pragma unroll
                for (int mi = 0; mi < 2; mi++)
#pragma unroll
                    for (int ni = 0; ni < 4; ni++)
                        mma_bf16(acc[mi][ni][0], acc[mi][ni][1], acc[mi][ni][2], acc[mi][ni][3],
                                 ax[mi][0], ax[mi][1], ax[mi][2], ax[mi][3],
                                 bx[ni][0], bx[ni][1]);
                // A_hi x B_lo
#pragma unroll
                for (int ni = 0; ni < 4; ni++) {
                    int n = wn * 32 + ni * 8 + g;
                    bx[ni][0] = Bl[n * SB + kb + tig];
                    bx[ni][1] = Bl[n * SB + kb + tig + 4];
                }
#pragma unroll
                for (int mi = 0; mi < 2; mi++)
#pragma unroll
                    for (int ni = 0; ni < 4; ni++)
                        mma_bf16(acc[mi][ni][0], acc[mi][ni][1], acc[mi][ni][2], acc[mi][ni][3],
                                 ah[mi][0], ah[mi][1], ah[mi][2], ah[mi][3],
                                 bx[ni][0], bx[ni][1]);
            }
        }
        // -------- store prefetched chunk to other buffer --------
        if (have_next) {
            int nxt = cur ^ 1;
            unsigned* Ah = (unsigned*)(smem + nxt * BUFB + OFF_AH);
            unsigned* Al = (unsigned*)(smem + nxt * BUFB + OFF_AL);
            unsigned* Bh = (unsigned*)(smem + nxt * BUFB + OFF_BH);
            unsigned* Bl = (unsigned*)(smem + nxt * BUFB + OFF_BL);
#pragma unroll
            for (int j = 0; j < 8; j++) {
                unsigned hp, lp; cvt2(av[j], hp, lp);
                Ah[arow[j] * SA + akq[j]] = hp;
                Al[arow[j] * SA + akq[j]] = lp;
            }
#pragma unroll
            for (int j = 0; j < 4; j++) {
                unsigned hp, lp; cvt2(make_float2(bv0[j], bv1[j]), hp, lp);
                Bh[bn[j] * SB + ba[j]] = hp;
                Bl[bn[j] * SB + ba[j]] = lp;
            }
        }
        __syncthreads();
    }

    // -------- epilogue: stage C in smem (overlays load buffers) --------
    float* Cs = (float*)smem;
#pragma unroll
    for (int mi = 0; mi < 2; mi++)
#pragma unroll
        for (int ni = 0; ni < 4; ni++) {
            int r = wm * 32 + mi * 16 + g;
            int cc = wn * 32 + ni * 8 + tig * 2;
            Cs[r * CS_STRIDE + cc]           = acc[mi][ni][0];
            Cs[r * CS_STRIDE + cc + 1]       = acc[mi][ni][1];
            Cs[(r + 8) * CS_STRIDE + cc]     = acc[mi][ni][2];
            Cs[(r + 8) * CS_STRIDE + cc + 1] = acc[mi][ni][3];
        }
    __syncthreads();

    // coalesced Hfull stores: 2 rows x 16 float4 per warp-iter
#pragma unroll
    for (int it = 0; it < 8; it++) {
        int r = (t >> 4) + 16 * it;
        int c4 = (t & 15) * 4;
        if (row0 + r < N0) {
            float4 v = *(const float4*)(Cs + r * CS_STRIDE + c4);
            *(float4*)(g_Hfull + (size_t)(row0 + r) * D1 + c4) = v;
        }
    }
    // fused attention logits (one thread per row)
    if (t < 128) {
        int m = row0 + t;
        if (m < N0) {
            const float* rr = Cs + t * CS_STRIDE;
#pragma unroll
            for (int h = 0; h < H1N; h++) {
                float as = 0.f, ad = 0.f;
#pragma unroll
                for (int cc = 0; cc < C1N; cc++) {
                    float v = rr[h * C1N + cc];
                    as = fmaf(v, __ldg(&a_src[h * C1N + cc]), as);
                    ad = fmaf(v, __ldg(&a_dst[h * C1N + cc]), ad);
                }
                g_as1[m * H1N + h] = as;
                if (m < N1V) g_ad1[m * H1N + h] = ad;
            }
        }
    }
}

// ======================= edge passes, layer 1 =======================
__device__ __forceinline__ void red4(float* p, float a, float b, float c, float d) {
    asm volatile("red.global.add.v4.f32 [%0], {%1, %2, %3, %4};"
                 :: "l"(p), "f"(a), "f"(b), "f"(c), "f"(d) : "memory");
}

__device__ __forceinline__ void edge1_sd(const void* e1p, int e, int& s, int& d) {
    if (e < E1N) { s = eidx(e1p, e); d = eidx(e1p, (long long)E1N + e); }
    else { s = d = e - E1N; }
}

__global__ void k_edge1_pass1(const void* e1p) {
    int e = blockIdx.x * blockDim.x + threadIdx.x;
    if (e >= EL1) return;
    int s, d; edge1_sd(e1p, e, s, d);
    float4 s0 = *(const float4*)&g_as1[s * 8];
    float4 s1 = *(const float4*)&g_as1[s * 8 + 4];
    float4 d0 = *(const float4*)&g_ad1[d * 8];
    float4 d1 = *(const float4*)&g_ad1[d * 8 + 4];
    float a[8] = { s0.x + d0.x, s0.y + d0.y, s0.z + d0.z, s0.w + d0.w,
                   s1.x + d1.x, s1.y + d1.y, s1.z + d1.z, s1.w + d1.w };
    float ex[8];
#pragma unroll
    for (int h = 0; h < 8; h++) {
        float al = a[h] > 0.f ? a[h] : NEG * a[h];
        ex[h] = expf(al);
    }
    *(float4*)&g_ex1[(size_t)e * 8]     = make_float4(ex[0], ex[1], ex[2], ex[3]);
    *(float4*)&g_ex1[(size_t)e * 8 + 4] = make_float4(ex[4], ex[5], ex[6], ex[7]);
    red4(&g_s1[d * 8],     ex[0], ex[1], ex[2], ex[3]);
    red4(&g_s1[d * 8 + 4], ex[4], ex[5], ex[6], ex[7]);
}

__global__ void k_edge1_agg(const void* e1p) {
    int e = blockIdx.x * blockDim.x + threadIdx.x;
    if (e >= EL1) return;
    int s, d; edge1_sd(e1p, e, s, d);
    float4 e0 = *(const float4*)&g_ex1[(size_t)e * 8];
    float4 e1 = *(const float4*)&g_ex1[(size_t)e * 8 + 4];
    float4 t0 = *(const float4*)&g_s1[d * 8];
    float4 t1 = *(const float4*)&g_s1[d * 8 + 4];
    float w[8] = { e0.x / (t0.x + 1e-16f), e0.y / (t0.y + 1e-16f),
                   e0.z / (t0.z + 1e-16f), e0.w / (t0.w + 1e-16f),
                   e1.x / (t1.x + 1e-16f), e1.y / (t1.y + 1e-16f),
                   e1.z / (t1.z + 1e-16f), e1.w / (t1.w + 1e-16f) };
    const float4* hs = (const float4*)(g_Hfull + (size_t)s * D1);
    float* ob = g_out1 + d * D1;
#pragma unroll
    for (int h = 0; h < 8; h++) {
        float4 p = hs[h * 2], q = hs[h * 2 + 1];
        red4(ob + h * 8,     p.x * w[h], p.y * w[h], p.z * w[h], p.w * w[h]);
        red4(ob + h * 8 + 4, q.x * w[h], q.y * w[h], q.z * w[h], q.w * w[h]);
    }
}

// ---------------- +b1 then ELU ----------------
__global__ void k_elu(const float* __restrict__ b1) {
    int i = blockIdx.x * blockDim.x + threadIdx.x;
    if (i >= N1V * D1) return;
    float v = g_out1[i] + b1[i & (D1 - 1)];
    g_out1[i] = v > 0.f ? v : expm1f(v);
}

// ---------------- GEMM2 + layer-2 attention ----------------
__global__ void k_gemm2(const float* __restrict__ W2) {
    __shared__ float Ws[D1 * NCLS];
    for (int i = threadIdx.x; i < D1 * NCLS; i += blockDim.x) Ws[i] = W2[i];
    __syncthreads();
    int t = blockIdx.x * blockDim.x + threadIdx.x;
    if (t >= N1V * NCLS) return;
    int row = t / NCLS, col = t - row * NCLS;
    const float* hr = g_out1 + row * D1;
    float acc = 0.f;
#pragma unroll
    for (int k = 0; k < D1; k++) acc = fmaf(hr[k], Ws[k * NCLS + col], acc);
    g_H2[t] = acc;
}

__global__ void k_att2(const float* __restrict__ a_src, const float* __restrict__ a_dst) {
    int i = blockIdx.x * blockDim.x + threadIdx.x;
    if (i >= N1V) return;
    const float* hp = g_H2 + i * NCLS;
    float as = 0.f;
#pragma unroll
    for (int c = 0; c < NCLS; c++) as += hp[c] * a_src[c];
    g_as2[i] = as;
    if (i < N2V) {
        float ad = 0.f;
#pragma unroll
        for (int c = 0; c < NCLS; c++) ad += hp[c] * a_dst[c];
        g_ad2[i] = ad;
    }
}

__device__ __forceinline__ void edge2_sd(const void* e2p, int e, int& s, int& d) {
    if (e < E2N) { s = eidx(e2p, e); d = eidx(e2p, (long long)E2N + e); }
    else { s = d = e - E2N; }
}

__global__ void k_edge2_sum(const void* e2p) {
    int e = blockIdx.x * blockDim.x + threadIdx.x;
    if (e >= EL2) return;
    int s, d; edge2_sd(e2p, e, s, d);
    float al = g_as2[s] + g_ad2[d];
    al = al > 0.f ? al : NEG * al;
    atomicAdd(&g_s2[d], expf(al));
}

__global__ void k_edge2_agg(const void* e2p) {
    int t = blockIdx.x * blockDim.x + threadIdx.x;
    if (t >= EL2 * NCLS) return;
    int e = t / NCLS, c = t - e * NCLS;
    int s, d; edge2_sd(e2p, e, s, d);
    float al = g_as2[s] + g_ad2[d];
    al = al > 0.f ? al : NEG * al;
    float w = expf(al) / (g_s2[d] + 1e-16f);
    atomicAdd(&g_out2[d * NCLS + c], g_H2[s * NCLS + c] * w);
}

// ---------------- final: +b2, row log_softmax ----------------
__global__ void k_final(float* __restrict__ out, const float* __restrict__ b2) {
    int d = blockIdx.x;
    int lane = threadIdx.x;
    float v0 = (lane < NCLS) ? g_out2[d * NCLS + lane] + b2[lane] : -INFINITY;
    float v1 = (lane + 32 < NCLS) ? g_out2[d * NCLS + lane + 32] + b2[lane + 32] : -INFINITY;
    float m = fmaxf(v0, v1);
#pragma unroll
    for (int o = 16; o > 0; o >>= 1) m = fmaxf(m, __shfl_xor_sync(0xffffffffu, m, o));
    float s = ((lane < NCLS) ? expf(v0 - m) : 0.f) + ((lane + 32 < NCLS) ? expf(v1 - m) : 0.f);
#pragma unroll
    for (int o = 16; o > 0; o >>= 1) s += __shfl_xor_sync(0xffffffffu, s, o);
    float ls = m + logf(s);
    if (lane < NCLS) out[d * NCLS + lane] = v0 - ls;
    if (lane + 32 < NCLS) out[d * NCLS + lane + 32] = v1 - ls;
}

// ---------------- launch ----------------
extern "C" void kernel_launch(void* const* d_in, const int* in_sizes, int n_in,
                              void* d_out, int out_size) {
    const float* x = nullptr;
    const void* e1 = nullptr;
    const void* e2 = nullptr;
    const float *W1 = nullptr, *as1 = nullptr, *ad1 = nullptr, *b1 = nullptr;
    const float *W2 = nullptr, *as2 = nullptr, *ad2 = nullptr, *b2 = nullptr;

    for (int i = 0; i < n_in; i++) {
        switch (in_sizes[i]) {
            case N0 * F_IN:   x  = (const float*)d_in[i]; break;
            case 2 * E1N:     e1 = d_in[i]; break;
            case 2 * E2N:     e2 = d_in[i]; break;
            case F_IN * D1:
                W1  = (const float*)d_in[i];
                if (i + 3 < n_in) {
                    as1 = (const float*)d_in[i + 1];
                    ad1 = (const float*)d_in[i + 2];
                    b1  = (const float*)d_in[i + 3];
                }
                break;
            case D1 * NCLS:
                W2  = (const float*)d_in[i];
                if (i + 3 < n_in) {
                    as2 = (const float*)d_in[i + 1];
                    ad2 = (const float*)d_in[i + 2];
                    b2  = (const float*)d_in[i + 3];
                }
                break;
            default: break;
        }
    }

    float* out = (float*)d_out;
    const int TPB = 256;

    cudaFuncSetAttribute(k_gemm1_mma, cudaFuncAttributeMaxDynamicSharedMemorySize, SMEM_G1);

    k_detect<<<1, 32>>>(e1);
    k_init<<<1024, TPB>>>();
    k_gemm1_mma<<<(N0 + 127) / 128, TPB, SMEM_G1>>>(x, W1, as1, ad1);
    k_edge1_pass1<<<(EL1 + TPB - 1) / TPB, TPB>>>(e1);
    k_edge1_agg<<<(EL1 + TPB - 1) / TPB, TPB>>>(e1);
    k_elu<<<(N1V * D1 + TPB - 1) / TPB, TPB>>>(b1);
    k_gemm2<<<(N1V * NCLS + TPB - 1) / TPB, TPB>>>(W2);
    k_att2<<<(N1V + TPB - 1) / TPB, TPB>>>(as2, ad2);
    k_edge2_sum<<<(EL2 + TPB - 1) / TPB, TPB>>>(e2);
    k_edge2_agg<<<(EL2 * NCLS + TPB - 1) / TPB, TPB>>>(e2);
    k_final<<<N2V, 32>>>(out, b2);
}

// round 5
// speedup vs baseline: 1.9866x; 1.1327x over previous
#include <cuda_runtime.h>
#include <cuda_bf16.h>
#include <math.h>

#define N0   120000
#define N1V  12000
#define N2V  1024
#define E1N  300000
#define E2N  10240
#define F_IN 602
#define H1N  8
#define C1N  8
#define D1   64
#define NCLS 41
#define NEG  0.2f

#define EL1  (E1N + N1V)   // 312000
#define EL2  (E2N + N2V)   // 11264
#define KPAD 608           // 19 * 32

// ---------------- scratch ----------------
__device__ float          g_Hfull[(size_t)N0 * D1];
__device__ float          g_as1[N0 * H1N];
__device__ float          g_ad1[N1V * H1N];
__device__ float          g_s1[N1V * H1N];
__device__ float          g_ex1[(size_t)EL1 * H1N];
__device__ float          g_out1[N1V * D1];
__device__ float          g_H2[N1V * NCLS];
__device__ float          g_as2[N1V];
__device__ float          g_ad2[N2V];
__device__ float          g_s2[N2V];
__device__ float          g_out2[N2V * NCLS];
__device__ __nv_bfloat16  g_W1h[D1 * KPAD];    // [n][kpad]
__device__ __nv_bfloat16  g_W1l[D1 * KPAD];
__device__ int2           g_e1sd[EL1];
__device__ int2           g_e2sd[EL2];

// ================= prep: detect dtype, init accumulators, split W1, pack edges =================
__global__ void k_prep(const float* __restrict__ W1, const void* e1, const void* e2) {
    __shared__ int se64;
    if (threadIdx.x == 0) {
        const long long* p = (const long long*)e1;
        bool ok = true;
        for (int i = 0; i < 16; i++) {
            long long v = p[i];
            if (v < 0 || v >= (long long)N0) { ok = false; break; }
        }
        se64 = ok ? 1 : 0;
    }
    __syncthreads();
    int e64 = se64;
    int nt = gridDim.x * blockDim.x;
    int t0 = blockIdx.x * blockDim.x + threadIdx.x;

    for (int i = t0; i < N1V * D1; i += nt) g_out1[i] = 0.f;
    for (int i = t0; i < N1V * H1N; i += nt) g_s1[i] = 0.f;
    for (int i = t0; i < N2V * NCLS; i += nt) g_out2[i] = 0.f;
    for (int i = t0; i < N2V; i += nt) g_s2[i] = 0.f;

    for (int i = t0; i < D1 * KPAD; i += nt) {
        int n = i / KPAD, k = i - n * KPAD;
        float v = (k < F_IN) ? W1[(size_t)k * D1 + n] : 0.f;
        __nv_bfloat16 h = __float2bfloat16(v);
        g_W1h[i] = h;
        g_W1l[i] = __float2bfloat16(v - __bfloat162float(h));
    }
    for (int e = t0; e < EL1; e += nt) {
        int s, d;
        if (e < E1N) {
            if (e64) {
                s = (int)((const long long*)e1)[e];
                d = (int)((const long long*)e1)[E1N + e];
            } else {
                s = ((const int*)e1)[e];
                d = ((const int*)e1)[E1N + e];
            }
        } else { s = d = e - E1N; }
        g_e1sd[e] = make_int2(s, d);
    }
    for (int e = t0; e < EL2; e += nt) {
        int s, d;
        if (e < E2N) {
            if (e64) {
                s = (int)((const long long*)e2)[e];
                d = (int)((const long long*)e2)[E2N + e];
            } else {
                s = ((const int*)e2)[e];
                d = ((const int*)e2)[E2N + e];
            }
        } else { s = d = e - E2N; }
        g_e2sd[e] = make_int2(s, d);
    }
}

// ================= GEMM1: mma.sync bf16x3, ldmatrix consumer, cp.async B =================
#define KC      32
#define NCHUNK  19
#define SA_U32  20           // A row stride: 80 bytes (16B-aligned, conflict-free)
#define SRB     80           // row stride bytes (A and B)
#define A_BYTES (128 * SRB)  // 10240
#define B_BYTES (64 * SRB)   // 5120
#define OFF_AH  0
#define OFF_AL  10240
#define OFF_BH  20480
#define OFF_BL  25600
#define BUFB    30720
#define SMEM_G1 (2 * BUFB)   // 61440
#define CS_STRIDE 72

__device__ __forceinline__ unsigned smem_u32(const void* p) {
    unsigned a;
    asm("{ .reg .u64 t; cvta.to.shared.u64 t, %1; cvt.u32.u64 %0, t; }" : "=r"(a) : "l"(p));
    return a;
}

__device__ __forceinline__ void cvt2(float2 v, unsigned& hp, unsigned& lp) {
    __nv_bfloat16 hx = __float2bfloat16(v.x), hy = __float2bfloat16(v.y);
    float rx = v.x - __bfloat162float(hx), ry = v.y - __bfloat162float(hy);
    __nv_bfloat16 lx = __float2bfloat16(rx), ly = __float2bfloat16(ry);
    hp = ((unsigned)__bfloat16_as_ushort(hy) << 16) | __bfloat16_as_ushort(hx);
    lp = ((unsigned)__bfloat16_as_ushort(ly) << 16) | __bfloat16_as_ushort(lx);
}

__device__ __forceinline__ void mma_bf16(float* c,
                                         const unsigned* a,
                                         unsigned b0, unsigned b1) {
    asm volatile(
        "mma.sync.aligned.m16n8k16.row.col.f32.bf16.bf16.f32 "
        "{%0,%1,%2,%3}, {%4,%5,%6,%7}, {%8,%9}, {%0,%1,%2,%3};"
        : "+f"(c[0]), "+f"(c[1]), "+f"(c[2]), "+f"(c[3])
        : "r"(a[0]), "r"(a[1]), "r"(a[2]), "r"(a[3]), "r"(b0), "r"(b1));
}

__device__ __forceinline__ void ldm4(unsigned addr, unsigned* r) {
    asm volatile("ldmatrix.sync.aligned.m8n8.x4.shared.b16 {%0,%1,%2,%3}, [%4];"
                 : "=r"(r[0]), "=r"(r[1]), "=r"(r[2]), "=r"(r[3]) : "r"(addr));
}

__device__ __forceinline__ void cpa16(unsigned dst, const void* src) {
    asm volatile("cp.async.cg.shared.global [%0], [%1], 16;" :: "r"(dst), "l"(src));
}

__global__ void __launch_bounds__(256, 2)
k_gemm1_mma(const float* __restrict__ x,
            const float* __restrict__ a_src, const float* __restrict__ a_dst) {
    extern __shared__ unsigned char smem[];
    unsigned sb = smem_u32(smem);
    int t = threadIdx.x;
    int w = t >> 5, lane = t & 31;
    int g = lane >> 2, tig = lane & 3;
    int wm = w & 3, wn = w >> 2;
    int row0 = blockIdx.x * 128;

    float acc[2][4][4];
#pragma unroll
    for (int mi = 0; mi < 2; mi++)
#pragma unroll
        for (int ni = 0; ni < 4; ni++)
#pragma unroll
            for (int q = 0; q < 4; q++) acc[mi][ni][q] = 0.f;

    // B cp.async source offsets for this thread (one 16B chunk each for hi/lo)
    int bn = t >> 2, bq = t & 3;                       // n row, 16B quarter
    unsigned bdst_off = bn * SRB + bq * 16;            // within B region
    int bsrc_elem = bn * KPAD + bq * 8;                // bf16 elements (q*16 bytes)

    // lane-invariant ldmatrix offsets
    int arow = ((lane >> 3) & 1) * 8 + (lane & 7);
    unsigned a_loff = (unsigned)((wm * 32 + arow) * SRB + (lane >> 4) * 16);
    int brow = ((lane >> 4) << 3) + (lane & 7);
    unsigned b_loff = (unsigned)((wn * 32 + brow) * SRB + ((lane >> 3) & 1) * 16);

    // -------- prologue: chunk 0 --------
    {
        unsigned* Ah = (unsigned*)(smem + OFF_AH);
        unsigned* Al = (unsigned*)(smem + OFF_AL);
#pragma unroll
        for (int j = 0; j < 8; j++) {
            int idx = t + 256 * j;
            int row = idx >> 4, kq = idx & 15;
            float2 v = make_float2(0.f, 0.f);
            if (row0 + row < N0)
                v = *(const float2*)(x + (size_t)(row0 + row) * F_IN + 2 * kq);
            unsigned hp, lp; cvt2(v, hp, lp);
            Ah[row * SA_U32 + kq] = hp; Al[row * SA_U32 + kq] = lp;
        }
        cpa16(sb + OFF_BH + bdst_off, (const void*)(g_W1h + bsrc_elem));
        cpa16(sb + OFF_BL + bdst_off, (const void*)(g_W1l + bsrc_elem));
        asm volatile("cp.async.commit_group;");
        asm volatile("cp.async.wait_group 0;");
    }
    __syncthreads();

    for (int c = 0; c < NCHUNK; c++) {
        int cur = c & 1, nxt = cur ^ 1;
        bool have_next = (c + 1 < NCHUNK);
        float2 av[8];
        if (have_next) {
            int k0 = (c + 1) * KC;
            // B for next chunk via cp.async
            int ksrc = bsrc_elem + k0;
            cpa16(sb + nxt * BUFB + OFF_BH + bdst_off, (const void*)(g_W1h + ksrc));
            cpa16(sb + nxt * BUFB + OFF_BL + bdst_off, (const void*)(g_W1l + ksrc));
            asm volatile("cp.async.commit_group;");
            // A for next chunk into registers
#pragma unroll
            for (int j = 0; j < 8; j++) {
                int idx = t + 256 * j;
                int row = idx >> 4, kq = idx & 15;
                int gk = k0 + 2 * kq;
                float2 v = make_float2(0.f, 0.f);
                if (row0 + row < N0 && gk < F_IN)
                    v = *(const float2*)(x + (size_t)(row0 + row) * F_IN + gk);
                av[j] = v;
            }
        }
        // -------- compute on current buffer --------
        {
            unsigned abh = sb + cur * BUFB + OFF_AH + a_loff;
            unsigned abl = sb + cur * BUFB + OFF_AL + a_loff;
            unsigned bbh = sb + cur * BUFB + OFF_BH + b_loff;
            unsigned bbl = sb + cur * BUFB + OFF_BL + b_loff;
#pragma unroll
            for (int kb = 0; kb < 2; kb++) {
                unsigned ko = kb * 32;
                unsigned ah[2][4], al[2][4], bh[2][4], bl[2][4];
#pragma unroll
                for (int mi = 0; mi < 2; mi++) {
                    ldm4(abh + mi * (16 * SRB) + ko, ah[mi]);
                    ldm4(abl + mi * (16 * SRB) + ko, al[mi]);
                }
#pragma unroll
                for (int nb = 0; nb < 2; nb++) {
                    ldm4(bbh + nb * (16 * SRB) + ko, bh[nb]);
                    ldm4(bbl + nb * (16 * SRB) + ko, bl[nb]);
                }
#pragma unroll
                for (int mi = 0; mi < 2; mi++)
#pragma unroll
                    for (int nb = 0; nb < 2; nb++) {
                        mma_bf16(acc[mi][nb * 2 + 0], ah[mi], bh[nb][0], bh[nb][1]);
                        mma_bf16(acc[mi][nb * 2 + 1], ah[mi], bh[nb][2], bh[nb][3]);
                        mma_bf16(acc[mi][nb * 2 + 0], al[mi], bh[nb][0], bh[nb][1]);
                        mma_bf16(acc[mi][nb * 2 + 1], al[mi], bh[nb][2], bh[nb][3]);
                        mma_bf16(acc[mi][nb * 2 + 0], ah[mi], bl[nb][0], bl[nb][1]);
                        mma_bf16(acc[mi][nb * 2 + 1], ah[mi], bl[nb][2], bl[nb][3]);
                    }
            }
        }
        if (have_next) {
            unsigned* Ah = (unsigned*)(smem + nxt * BUFB + OFF_AH);
            unsigned* Al = (unsigned*)(smem + nxt * BUFB + OFF_AL);
#pragma unroll
            for (int j = 0; j < 8; j++) {
                int idx = t + 256 * j;
                int row = idx >> 4, kq = idx & 15;
                unsigned hp, lp; cvt2(av[j], hp, lp);
                Ah[row * SA_U32 + kq] = hp; Al[row * SA_U32 + kq] = lp;
            }
        }
        asm volatile("cp.async.wait_group 0;");
        __syncthreads();
    }

    // -------- epilogue: stage C in smem, coalesced stores + fused logits --------
    float* Cs = (float*)smem;
#pragma unroll
    for (int mi = 0; mi < 2; mi++)
#pragma unroll
        for (int ni = 0; ni < 4; ni++) {
            int r = wm * 32 + mi * 16 + g;
            int cc = wn * 32 + ni * 8 + tig * 2;
            Cs[r * CS_STRIDE + cc]           = acc[mi][ni][0];
            Cs[r * CS_STRIDE + cc + 1]       = acc[mi][ni][1];
            Cs[(r + 8) * CS_STRIDE + cc]     = acc[mi][ni][2];
            Cs[(r + 8) * CS_STRIDE + cc + 1] = acc[mi][ni][3];
        }
    __syncthreads();

#pragma unroll
    for (int it = 0; it < 8; it++) {
        int r = (t >> 4) + 16 * it;
        int c4 = (t & 15) * 4;
        if (row0 + r < N0) {
            float4 v = *(const float4*)(Cs + r * CS_STRIDE + c4);
            *(float4*)(g_Hfull + (size_t)(row0 + r) * D1 + c4) = v;
        }
    }
    if (t < 128) {
        int m = row0 + t;
        if (m < N0) {
            const float* rr = Cs + t * CS_STRIDE;
#pragma unroll
            for (int h = 0; h < H1N; h++) {
                float as = 0.f, ad = 0.f;
#pragma unroll
                for (int cc = 0; cc < C1N; cc++) {
                    float v = rr[h * C1N + cc];
                    as = fmaf(v, __ldg(&a_src[h * C1N + cc]), as);
                    ad = fmaf(v, __ldg(&a_dst[h * C1N + cc]), ad);
                }
                g_as1[m * H1N + h] = as;
                if (m < N1V) g_ad1[m * H1N + h] = ad;
            }
        }
    }
}

// ================= edge passes, layer 1 =================
__device__ __forceinline__ void red4(float* p, float a, float b, float c, float d) {
    asm volatile("red.global.add.v4.f32 [%0], {%1, %2, %3, %4};"
                 :: "l"(p), "f"(a), "f"(b), "f"(c), "f"(d) : "memory");
}

__global__ void k_edge1_pass1() {
    int b = blockIdx.x * blockDim.x + threadIdx.x;
    int e0 = b * 2;
    if (e0 >= EL1) return;
    bool two = (e0 + 1 < EL1);
    int2 sd0 = g_e1sd[e0];
    int2 sd1 = two ? g_e1sd[e0 + 1] : sd0;

    float4 sa0 = __ldg((const float4*)&g_as1[sd0.x * 8]);
    float4 sb0 = __ldg((const float4*)&g_as1[sd0.x * 8 + 4]);
    float4 sa1 = __ldg((const float4*)&g_as1[sd1.x * 8]);
    float4 sb1 = __ldg((const float4*)&g_as1[sd1.x * 8 + 4]);
    float4 da0 = __ldg((const float4*)&g_ad1[sd0.y * 8]);
    float4 db0 = __ldg((const float4*)&g_ad1[sd0.y * 8 + 4]);
    float4 da1 = __ldg((const float4*)&g_ad1[sd1.y * 8]);
    float4 db1 = __ldg((const float4*)&g_ad1[sd1.y * 8 + 4]);

    float a0[8] = { sa0.x + da0.x, sa0.y + da0.y, sa0.z + da0.z, sa0.w + da0.w,
                    sb0.x + db0.x, sb0.y + db0.y, sb0.z + db0.z, sb0.w + db0.w };
    float a1[8] = { sa1.x + da1.x, sa1.y + da1.y, sa1.z + da1.z, sa1.w + da1.w,
                    sb1.x + db1.x, sb1.y + db1.y, sb1.z + db1.z, sb1.w + db1.w };
    float e0v[8], e1v[8];
#pragma unroll
    for (int h = 0; h < 8; h++) {
        float v0 = a0[h] > 0.f ? a0[h] : NEG * a0[h];
        float v1 = a1[h] > 0.f ? a1[h] : NEG * a1[h];
        e0v[h] = expf(v0); e1v[h] = expf(v1);
    }
    *(float4*)&g_ex1[(size_t)e0 * 8]     = make_float4(e0v[0], e0v[1], e0v[2], e0v[3]);
    *(float4*)&g_ex1[(size_t)e0 * 8 + 4] = make_float4(e0v[4], e0v[5], e0v[6], e0v[7]);
    red4(&g_s1[sd0.y * 8],     e0v[0], e0v[1], e0v[2], e0v[3]);
    red4(&g_s1[sd0.y * 8 + 4], e0v[4], e0v[5], e0v[6], e0v[7]);
    if (two) {
        *(float4*)&g_ex1[(size_t)(e0 + 1) * 8]     = make_float4(e1v[0], e1v[1], e1v[2], e1v[3]);
        *(float4*)&g_ex1[(size_t)(e0 + 1) * 8 + 4] = make_float4(e1v[4], e1v[5], e1v[6], e1v[7]);
        red4(&g_s1[sd1.y * 8],     e1v[0], e1v[1], e1v[2], e1v[3]);
        red4(&g_s1[sd1.y * 8 + 4], e1v[4], e1v[5], e1v[6], e1v[7]);
    }
}

__global__ void k_edge1_agg() {
    int e = blockIdx.x * blockDim.x + threadIdx.x;
    if (e >= EL1) return;
    int2 sd = g_e1sd[e];
    float4 e0 = __ldg((const float4*)&g_ex1[(size_t)e * 8]);
    float4 e1 = __ldg((const float4*)&g_ex1[(size_t)e * 8 + 4]);
    float4 t0 = __ldg((const float4*)&g_s1[sd.y * 8]);
    float4 t1 = __ldg((const float4*)&g_s1[sd.y * 8 + 4]);
    float w[8] = { e0.x / (t0.x + 1e-16f), e0.y / (t0.y + 1e-16f),
                   e0.z / (t0.z + 1e-16f), e0.w / (t0.w + 1e-16f),
                   e1.x / (t1.x + 1e-16f), e1.y / (t1.y + 1e-16f),
                   e1.z / (t1.z + 1e-16f), e1.w / (t1.w + 1e-16f) };
    const float4* hs = (const float4*)(g_Hfull + (size_t)sd.x * D1);
    float* ob = g_out1 + sd.y * D1;
#pragma unroll
    for (int h = 0; h < 8; h++) {
        float4 p = __ldg(&hs[h * 2]), q = __ldg(&hs[h * 2 + 1]);
        red4(ob + h * 8,     p.x * w[h], p.y * w[h], p.z * w[h], p.w * w[h]);
        red4(ob + h * 8 + 4, q.x * w[h], q.y * w[h], q.z * w[h], q.w * w[h]);
    }
}

__global__ void k_elu(const float* __restrict__ b1) {
    int i = blockIdx.x * blockDim.x + threadIdx.x;
    if (i >= N1V * D1) return;
    float v = g_out1[i] + b1[i & (D1 - 1)];
    g_out1[i] = v > 0.f ? v : expm1f(v);
}

__global__ void k_gemm2(const float* __restrict__ W2) {
    __shared__ float Ws[D1 * NCLS];
    for (int i = threadIdx.x; i < D1 * NCLS; i += blockDim.x) Ws[i] = W2[i];
    __syncthreads();
    int t = blockIdx.x * blockDim.x + threadIdx.x;
    if (t >= N1V * NCLS) return;
    int row = t / NCLS, col = t - row * NCLS;
    const float* hr = g_out1 + row * D1;
    float acc = 0.f;
#pragma unroll
    for (int k = 0; k < D1; k++) acc = fmaf(hr[k], Ws[k * NCLS + col], acc);
    g_H2[t] = acc;
}

__global__ void k_att2(const float* __restrict__ a_src, const float* __restrict__ a_dst) {
    int i = blockIdx.x * blockDim.x + threadIdx.x;
    if (i >= N1V) return;
    const float* hp = g_H2 + i * NCLS;
    float as = 0.f;
#pragma unroll
    for (int c = 0; c < NCLS; c++) as += hp[c] * a_src[c];
    g_as2[i] = as;
    if (i < N2V) {
        float ad = 0.f;
#pragma unroll
        for (int c = 0; c < NCLS; c++) ad += hp[c] * a_dst[c];
        g_ad2[i] = ad;
    }
}

__global__ void k_edge2_sum() {
    int e = blockIdx.x * blockDim.x + threadIdx.x;
    if (e >= EL2) return;
    int2 sd = g_e2sd[e];
    float al = g_as2[sd.x] + g_ad2[sd.y];
    al = al > 0.f ? al : NEG * al;
    atomicAdd(&g_s2[sd.y], expf(al));
}

__global__ void k_edge2_agg() {
    int t = blockIdx.x * blockDim.x + threadIdx.x;
    if (t >= EL2 * NCLS) return;
    int e = t / NCLS, c = t - e * NCLS;
    int2 sd = g_e2sd[e];
    float al = g_as2[sd.x] + g_ad2[sd.y];
    al = al > 0.f ? al : NEG * al;
    float w = expf(al) / (g_s2[sd.y] + 1e-16f);
    atomicAdd(&g_out2[sd.y * NCLS + c], g_H2[sd.x * NCLS + c] * w);
}

__global__ void k_final(float* __restrict__ out, const float* __restrict__ b2) {
    int d = blockIdx.x;
    int lane = threadIdx.x;
    float v0 = (lane < NCLS) ? g_out2[d * NCLS + lane] + b2[lane] : -INFINITY;
    float v1 = (lane + 32 < NCLS) ? g_out2[d * NCLS + lane + 32] + b2[lane + 32] : -INFINITY;
    float m = fmaxf(v0, v1);
#pragma unroll
    for (int o = 16; o > 0; o >>= 1) m = fmaxf(m, __shfl_xor_sync(0xffffffffu, m, o));
    float s = ((lane < NCLS) ? expf(v0 - m) : 0.f) + ((lane + 32 < NCLS) ? expf(v1 - m) : 0.f);
#pragma unroll
    for (int o = 16; o > 0; o >>= 1) s += __shfl_xor_sync(0xffffffffu, s, o);
    float ls = m + logf(s);
    if (lane < NCLS) out[d * NCLS + lane] = v0 - ls;
    if (lane + 32 < NCLS) out[d * NCLS + lane + 32] = v1 - ls;
}

// ---------------- launch ----------------
extern "C" void kernel_launch(void* const* d_in, const int* in_sizes, int n_in,
                              void* d_out, int out_size) {
    const float* x = nullptr;
    const void* e1 = nullptr;
    const void* e2 = nullptr;
    const float *W1 = nullptr, *as1 = nullptr, *ad1 = nullptr, *b1 = nullptr;
    const float *W2 = nullptr, *as2 = nullptr, *ad2 = nullptr, *b2 = nullptr;

    for (int i = 0; i < n_in; i++) {
        switch (in_sizes[i]) {
            case N0 * F_IN:   x  = (const float*)d_in[i]; break;
            case 2 * E1N:     e1 = d_in[i]; break;
            case 2 * E2N:     e2 = d_in[i]; break;
            case F_IN * D1:
                W1  = (const float*)d_in[i];
                if (i + 3 < n_in) {
                    as1 = (const float*)d_in[i + 1];
                    ad1 = (const float*)d_in[i + 2];
                    b1  = (const float*)d_in[i + 3];
                }
                break;
            case D1 * NCLS:
                W2  = (const float*)d_in[i];
                if (i + 3 < n_in) {
                    as2 = (const float*)d_in[i + 1];
                    ad2 = (const float*)d_in[i + 2];
                    b2  = (const float*)d_in[i + 3];
                }
                break;
            default: break;
        }
    }

    float* out = (float*)d_out;
    const int TPB = 256;

    cudaFuncSetAttribute(k_gemm1_mma, cudaFuncAttributeMaxDynamicSharedMemorySize, SMEM_G1);

    k_prep<<<512, TPB>>>(W1, e1, e2);
    k_gemm1_mma<<<(N0 + 127) / 128, TPB, SMEM_G1>>>(x, as1, ad1);
    k_edge1_pass1<<<(EL1 / 2 + TPB - 1) / TPB, TPB>>>();
    k_edge1_agg<<<(EL1 + TPB - 1) / TPB, TPB>>>();
    k_elu<<<(N1V * D1 + TPB - 1) / TPB, TPB>>>(b1);
    k_gemm2<<<(N1V * NCLS + TPB - 1) / TPB, TPB>>>(W2);
    k_att2<<<(N1V + TPB - 1) / TPB, TPB>>>(as2, ad2);
    k_edge2_sum<<<(EL2 + TPB - 1) / TPB, TPB>>>();
    k_edge2_agg<<<(EL2 * NCLS + TPB - 1) / TPB, TPB>>>();
    k_final<<<N2V, 32>>>(out, b2);
}

// round 6
// speedup vs baseline: 2.0533x; 1.0336x over previous
#include <cuda_runtime.h>
#include <cuda_bf16.h>
#include <math.h>

#define N0   120000
#define N1V  12000
#define N2V  1024
#define E1N  300000
#define E2N  10240
#define F_IN 602
#define H1N  8
#define C1N  8
#define D1   64
#define NCLS 41
#define NEG  0.2f

#define EL1  (E1N + N1V)   // 312000
#define EL2  (E2N + N2V)   // 11264
#define KPAD 608

// ---------------- scratch ----------------
__device__ float          g_Hfull[(size_t)N0 * D1];
__device__ float          g_as1[N0 * H1N];
__device__ float          g_ad1[N1V * H1N];
__device__ float          g_ex1[(size_t)EL1 * H1N];
__device__ float          g_out1[N1V * D1];
__device__ float          g_H2[N1V * NCLS];
__device__ float          g_as2[N1V];
__device__ float          g_ad2[N2V];
__device__ float          g_s2[N2V];
__device__ float          g_out2[N2V * NCLS];
__device__ __nv_bfloat16  g_W1h[D1 * KPAD];
__device__ __nv_bfloat16  g_W1l[D1 * KPAD];
__device__ int2           g_e1sd[EL1];
__device__ int2           g_e2sd[EL2];
// CSR for layer-1 dst grouping
__device__ int            g_deg1[N1V];
__device__ int            g_start1[N1V];
__device__ int            g_cur1[N1V];
__device__ int            g_csrc1[EL1];

// ================= prep =================
__global__ void k_prep(const float* __restrict__ W1, const void* e1, const void* e2) {
    __shared__ int se64;
    if (threadIdx.x == 0) {
        const long long* p = (const long long*)e1;
        bool ok = true;
        for (int i = 0; i < 16; i++) {
            long long v = p[i];
            if (v < 0 || v >= (long long)N0) { ok = false; break; }
        }
        se64 = ok ? 1 : 0;
    }
    __syncthreads();
    int e64 = se64;
    int nt = gridDim.x * blockDim.x;
    int t0 = blockIdx.x * blockDim.x + threadIdx.x;

    for (int i = t0; i < N1V; i += nt) g_deg1[i] = 0;
    for (int i = t0; i < N2V * NCLS; i += nt) g_out2[i] = 0.f;
    for (int i = t0; i < N2V; i += nt) g_s2[i] = 0.f;

    for (int i = t0; i < D1 * KPAD; i += nt) {
        int n = i / KPAD, k = i - n * KPAD;
        float v = (k < F_IN) ? W1[(size_t)k * D1 + n] : 0.f;
        __nv_bfloat16 h = __float2bfloat16(v);
        g_W1h[i] = h;
        g_W1l[i] = __float2bfloat16(v - __bfloat162float(h));
    }
    for (int e = t0; e < EL1; e += nt) {
        int s, d;
        if (e < E1N) {
            if (e64) {
                s = (int)((const long long*)e1)[e];
                d = (int)((const long long*)e1)[E1N + e];
            } else {
                s = ((const int*)e1)[e];
                d = ((const int*)e1)[E1N + e];
            }
        } else { s = d = e - E1N; }
        g_e1sd[e] = make_int2(s, d);
    }
    for (int e = t0; e < EL2; e += nt) {
        int s, d;
        if (e < E2N) {
            if (e64) {
                s = (int)((const long long*)e2)[e];
                d = (int)((const long long*)e2)[E2N + e];
            } else {
                s = ((const int*)e2)[e];
                d = ((const int*)e2)[E2N + e];
            }
        } else { s = d = e - E2N; }
        g_e2sd[e] = make_int2(s, d);
    }
}

// ================= CSR build =================
__global__ void k_count() {
    int e = blockIdx.x * blockDim.x + threadIdx.x;
    if (e >= EL1) return;
    atomicAdd(&g_deg1[g_e1sd[e].y], 1);
}

__global__ void k_scan() {   // single block, 1024 threads
    __shared__ int sh[1024];
    __shared__ int s_carry;
    int t = threadIdx.x;
    if (t == 0) s_carry = 0;
    __syncthreads();
    for (int chunk = 0; chunk < (N1V + 1023) / 1024; chunk++) {
        int i = chunk * 1024 + t;
        int v = (i < N1V) ? g_deg1[i] : 0;
        sh[t] = v;
        __syncthreads();
        // Hillis-Steele inclusive scan
        for (int o = 1; o < 1024; o <<= 1) {
            int add = (t >= o) ? sh[t - o] : 0;
            __syncthreads();
            sh[t] += add;
            __syncthreads();
        }
        int excl = sh[t] - v + s_carry;
        if (i < N1V) { g_start1[i] = excl; g_cur1[i] = excl; }
        __syncthreads();
        if (t == 0) s_carry += sh[1023];
        __syncthreads();
    }
}

__global__ void k_scatter() {
    int e = blockIdx.x * blockDim.x + threadIdx.x;
    if (e >= EL1) return;
    int2 sd = g_e1sd[e];
    int pos = atomicAdd(&g_cur1[sd.y], 1);
    g_csrc1[pos] = sd.x;
}

// ================= GEMM1: mma.sync bf16x3, ldmatrix, cp.async B =================
#define KC      32
#define NCHUNK  19
#define SA_U32  20
#define SRB     80
#define OFF_AH  0
#define OFF_AL  10240
#define OFF_BH  20480
#define OFF_BL  25600
#define BUFB    30720
#define SMEM_G1 (2 * BUFB)
#define CS_STRIDE 72

__device__ __forceinline__ unsigned smem_u32(const void* p) {
    unsigned a;
    asm("{ .reg .u64 t; cvta.to.shared.u64 t, %1; cvt.u32.u64 %0, t; }" : "=r"(a) : "l"(p));
    return a;
}

__device__ __forceinline__ void cvt2(float2 v, unsigned& hp, unsigned& lp) {
    __nv_bfloat16 hx = __float2bfloat16(v.x), hy = __float2bfloat16(v.y);
    float rx = v.x - __bfloat162float(hx), ry = v.y - __bfloat162float(hy);
    __nv_bfloat16 lx = __float2bfloat16(rx), ly = __float2bfloat16(ry);
    hp = ((unsigned)__bfloat16_as_ushort(hy) << 16) | __bfloat16_as_ushort(hx);
    lp = ((unsigned)__bfloat16_as_ushort(ly) << 16) | __bfloat16_as_ushort(lx);
}

__device__ __forceinline__ void mma_bf16(float* c, const unsigned* a, unsigned b0, unsigned b1) {
    asm volatile(
        "mma.sync.aligned.m16n8k16.row.col.f32.bf16.bf16.f32 "
        "{%0,%1,%2,%3}, {%4,%5,%6,%7}, {%8,%9}, {%0,%1,%2,%3};"
        : "+f"(c[0]), "+f"(c[1]), "+f"(c[2]), "+f"(c[3])
        : "r"(a[0]), "r"(a[1]), "r"(a[2]), "r"(a[3]), "r"(b0), "r"(b1));
}

__device__ __forceinline__ void ldm4(unsigned addr, unsigned* r) {
    asm volatile("ldmatrix.sync.aligned.m8n8.x4.shared.b16 {%0,%1,%2,%3}, [%4];"
                 : "=r"(r[0]), "=r"(r[1]), "=r"(r[2]), "=r"(r[3]) : "r"(addr));
}

__device__ __forceinline__ void cpa16(unsigned dst, const void* src) {
    asm volatile("cp.async.cg.shared.global [%0], [%1], 16;" :: "r"(dst), "l"(src));
}

__global__ void __launch_bounds__(256, 2)
k_gemm1_mma(const float* __restrict__ x,
            const float* __restrict__ a_src, const float* __restrict__ a_dst) {
    extern __shared__ unsigned char smem[];
    unsigned sb = smem_u32(smem);
    int t = threadIdx.x;
    int w = t >> 5, lane = t & 31;
    int g = lane >> 2, tig = lane & 3;
    int wm = w & 3, wn = w >> 2;
    int row0 = blockIdx.x * 128;

    float acc[2][4][4];
#pragma unroll
    for (int mi = 0; mi < 2; mi++)
#pragma unroll
        for (int ni = 0; ni < 4; ni++)
#pragma unroll
            for (int q = 0; q < 4; q++) acc[mi][ni][q] = 0.f;

    int bn = t >> 2, bq = t & 3;
    unsigned bdst_off = bn * SRB + bq * 16;
    int bsrc_elem = bn * KPAD + bq * 8;

    int arow = ((lane >> 3) & 1) * 8 + (lane & 7);
    unsigned a_loff = (unsigned)((wm * 32 + arow) * SRB + (lane >> 4) * 16);
    int brow = ((lane >> 4) << 3) + (lane & 7);
    unsigned b_loff = (unsigned)((wn * 32 + brow) * SRB + ((lane >> 3) & 1) * 16);

    {
        unsigned* Ah = (unsigned*)(smem + OFF_AH);
        unsigned* Al = (unsigned*)(smem + OFF_AL);
#pragma unroll
        for (int j = 0; j < 8; j++) {
            int idx = t + 256 * j;
            int row = idx >> 4, kq = idx & 15;
            float2 v = make_float2(0.f, 0.f);
            if (row0 + row < N0)
                v = *(const float2*)(x + (size_t)(row0 + row) * F_IN + 2 * kq);
            unsigned hp, lp; cvt2(v, hp, lp);
            Ah[row * SA_U32 + kq] = hp; Al[row * SA_U32 + kq] = lp;
        }
        cpa16(sb + OFF_BH + bdst_off, (const void*)(g_W1h + bsrc_elem));
        cpa16(sb + OFF_BL + bdst_off, (const void*)(g_W1l + bsrc_elem));
        asm volatile("cp.async.commit_group;");
        asm volatile("cp.async.wait_group 0;");
    }
    __syncthreads();

    for (int c = 0; c < NCHUNK; c++) {
        int cur = c & 1, nxt = cur ^ 1;
        bool have_next = (c + 1 < NCHUNK);
        float2 av[8];
        if (have_next) {
            int k0 = (c + 1) * KC;
            int ksrc = bsrc_elem + k0;
            cpa16(sb + nxt * BUFB + OFF_BH + bdst_off, (const void*)(g_W1h + ksrc));
            cpa16(sb + nxt * BUFB + OFF_BL + bdst_off, (const void*)(g_W1l + ksrc));
            asm volatile("cp.async.commit_group;");
#pragma unroll
            for (int j = 0; j < 8; j++) {
                int idx = t + 256 * j;
                int row = idx >> 4, kq = idx & 15;
                int gk = k0 + 2 * kq;
                float2 v = make_float2(0.f, 0.f);
                if (row0 + row < N0 && gk < F_IN)
                    v = *(const float2*)(x + (size_t)(row0 + row) * F_IN + gk);
                av[j] = v;
            }
        }
        {
            unsigned abh = sb + cur * BUFB + OFF_AH + a_loff;
            unsigned abl = sb + cur * BUFB + OFF_AL + a_loff;
            unsigned bbh = sb + cur * BUFB + OFF_BH + b_loff;
            unsigned bbl = sb + cur * BUFB + OFF_BL + b_loff;
#pragma unroll
            for (int kb = 0; kb < 2; kb++) {
                unsigned ko = kb * 32;
                unsigned ah[2][4], al[2][4], bh[2][4], bl[2][4];
#pragma unroll
                for (int mi = 0; mi < 2; mi++) {
                    ldm4(abh + mi * (16 * SRB) + ko, ah[mi]);
                    ldm4(abl + mi * (16 * SRB) + ko, al[mi]);
                }
#pragma unroll
                for (int nb = 0; nb < 2; nb++) {
                    ldm4(bbh + nb * (16 * SRB) + ko, bh[nb]);
                    ldm4(bbl + nb * (16 * SRB) + ko, bl[nb]);
                }
#pragma unroll
                for (int mi = 0; mi < 2; mi++)
#pragma unroll
                    for (int nb = 0; nb < 2; nb++) {
                        mma_bf16(acc[mi][nb * 2 + 0], ah[mi], bh[nb][0], bh[nb][1]);
                        mma_bf16(acc[mi][nb * 2 + 1], ah[mi], bh[nb][2], bh[nb][3]);
                        mma_bf16(acc[mi][nb * 2 + 0], al[mi], bh[nb][0], bh[nb][1]);
                        mma_bf16(acc[mi][nb * 2 + 1], al[mi], bh[nb][2], bh[nb][3]);
                        mma_bf16(acc[mi][nb * 2 + 0], ah[mi], bl[nb][0], bl[nb][1]);
                        mma_bf16(acc[mi][nb * 2 + 1], ah[mi], bl[nb][2], bl[nb][3]);
                    }
            }
        }
        if (have_next) {
            unsigned* Ah = (unsigned*)(smem + nxt * BUFB + OFF_AH);
            unsigned* Al = (unsigned*)(smem + nxt * BUFB + OFF_AL);
#pragma unroll
            for (int j = 0; j < 8; j++) {
                int idx = t + 256 * j;
                int row = idx >> 4, kq = idx & 15;
                unsigned hp, lp; cvt2(av[j], hp, lp);
                Ah[row * SA_U32 + kq] = hp; Al[row * SA_U32 + kq] = lp;
            }
        }
        asm volatile("cp.async.wait_group 0;");
        __syncthreads();
    }

    float* Cs = (float*)smem;
#pragma unroll
    for (int mi = 0; mi < 2; mi++)
#pragma unroll
        for (int ni = 0; ni < 4; ni++) {
            int r = wm * 32 + mi * 16 + g;
            int cc = wn * 32 + ni * 8 + tig * 2;
            Cs[r * CS_STRIDE + cc]           = acc[mi][ni][0];
            Cs[r * CS_STRIDE + cc + 1]       = acc[mi][ni][1];
            Cs[(r + 8) * CS_STRIDE + cc]     = acc[mi][ni][2];
            Cs[(r + 8) * CS_STRIDE + cc + 1] = acc[mi][ni][3];
        }
    __syncthreads();

#pragma unroll
    for (int it = 0; it < 8; it++) {
        int r = (t >> 4) + 16 * it;
        int c4 = (t & 15) * 4;
        if (row0 + r < N0) {
            float4 v = *(const float4*)(Cs + r * CS_STRIDE + c4);
            *(float4*)(g_Hfull + (size_t)(row0 + r) * D1 + c4) = v;
        }
    }
    if (t < 128) {
        int m = row0 + t;
        if (m < N0) {
            const float* rr = Cs + t * CS_STRIDE;
#pragma unroll
            for (int h = 0; h < H1N; h++) {
                float as = 0.f, ad = 0.f;
#pragma unroll
                for (int cc = 0; cc < C1N; cc++) {
                    float v = rr[h * C1N + cc];
                    as = fmaf(v, __ldg(&a_src[h * C1N + cc]), as);
                    ad = fmaf(v, __ldg(&a_dst[h * C1N + cc]), ad);
                }
                g_as1[m * H1N + h] = as;
                if (m < N1V) g_ad1[m * H1N + h] = ad;
            }
        }
    }
}

// ================= fused layer-1 softmax + aggregate + bias + ELU (warp per dst) =================
__global__ void __launch_bounds__(256)
k_edge1_fused(const float* __restrict__ b1) {
    int node = (blockIdx.x * blockDim.x + threadIdx.x) >> 5;
    int lane = threadIdx.x & 31;
    if (node >= N1V) return;
    int start = g_start1[node];
    int deg = g_deg1[node];
    int end = start + deg;

    float4 adA = __ldg((const float4*)&g_ad1[node * 8]);
    float4 adB = __ldg((const float4*)&g_ad1[node * 8 + 4]);
    float sum[8] = {0.f, 0.f, 0.f, 0.f, 0.f, 0.f, 0.f, 0.f};

    // phase 1: exp(leaky(alpha)) per (edge, head); cache to g_ex1; partial head-sums
    for (int e = start + lane; e < end; e += 32) {
        int s = __ldg(&g_csrc1[e]);
        float4 sa = __ldg((const float4*)&g_as1[s * 8]);
        float4 sbv = __ldg((const float4*)&g_as1[s * 8 + 4]);
        float a[8] = { sa.x + adA.x, sa.y + adA.y, sa.z + adA.z, sa.w + adA.w,
                       sbv.x + adB.x, sbv.y + adB.y, sbv.z + adB.z, sbv.w + adB.w };
        float ex[8];
#pragma unroll
        for (int h = 0; h < 8; h++) {
            float v = a[h] > 0.f ? a[h] : NEG * a[h];
            ex[h] = expf(v);
            sum[h] += ex[h];
        }
        *(float4*)&g_ex1[(size_t)e * 8]     = make_float4(ex[0], ex[1], ex[2], ex[3]);
        *(float4*)&g_ex1[(size_t)e * 8 + 4] = make_float4(ex[4], ex[5], ex[6], ex[7]);
    }
#pragma unroll
    for (int h = 0; h < 8; h++)
#pragma unroll
        for (int o = 16; o > 0; o >>= 1)
            sum[h] += __shfl_xor_sync(0xffffffffu, sum[h], o);

    int myh = lane >> 2;   // head owning columns 2*lane, 2*lane+1
    float myr = 1.f / (sum[myh] + 1e-16f);

    // phase 2: gather weighted sum; lane owns 2 of 64 columns
    float ax = 0.f, ay = 0.f;
    for (int e = start; e < end; e++) {
        int s = __ldg(&g_csrc1[e]);
        float wgt = __ldg(&g_ex1[(size_t)e * 8 + myh]) * myr;
        float2 hv = __ldg((const float2*)&g_Hfull[(size_t)s * D1 + 2 * lane]);
        ax = fmaf(wgt, hv.x, ax);
        ay = fmaf(wgt, hv.y, ay);
    }
    float bx = __ldg(&b1[2 * lane]), by = __ldg(&b1[2 * lane + 1]);
    float vx = ax + bx; vx = vx > 0.f ? vx : expm1f(vx);
    float vy = ay + by; vy = vy > 0.f ? vy : expm1f(vy);
    *(float2*)&g_out1[node * D1 + 2 * lane] = make_float2(vx, vy);
}

// ================= layer 2 =================
__global__ void k_gemm2(const float* __restrict__ W2) {
    __shared__ float Ws[D1 * NCLS];
    for (int i = threadIdx.x; i < D1 * NCLS; i += blockDim.x) Ws[i] = W2[i];
    __syncthreads();
    int t = blockIdx.x * blockDim.x + threadIdx.x;
    if (t >= N1V * NCLS) return;
    int row = t / NCLS, col = t - row * NCLS;
    const float* hr = g_out1 + row * D1;
    float acc = 0.f;
#pragma unroll
    for (int k = 0; k < D1; k++) acc = fmaf(hr[k], Ws[k * NCLS + col], acc);
    g_H2[t] = acc;
}

__global__ void k_att2(const float* __restrict__ a_src, const float* __restrict__ a_dst) {
    int i = blockIdx.x * blockDim.x + threadIdx.x;
    if (i >= N1V) return;
    const float* hp = g_H2 + i * NCLS;
    float as = 0.f;
#pragma unroll
    for (int c = 0; c < NCLS; c++) as += hp[c] * a_src[c];
    g_as2[i] = as;
    if (i < N2V) {
        float ad = 0.f;
#pragma unroll
        for (int c = 0; c < NCLS; c++) ad += hp[c] * a_dst[c];
        g_ad2[i] = ad;
    }
}

__global__ void k_edge2_sum() {
    int e = blockIdx.x * blockDim.x + threadIdx.x;
    if (e >= EL2) return;
    int2 sd = g_e2sd[e];
    float al = g_as2[sd.x] + g_ad2[sd.y];
    al = al > 0.f ? al : NEG * al;
    atomicAdd(&g_s2[sd.y], expf(al));
}

__global__ void k_edge2_agg() {
    int t = blockIdx.x * blockDim.x + threadIdx.x;
    if (t >= EL2 * NCLS) return;
    int e = t / NCLS, c = t - e * NCLS;
    int2 sd = g_e2sd[e];
    float al = g_as2[sd.x] + g_ad2[sd.y];
    al = al > 0.f ? al : NEG * al;
    float w = expf(al) / (g_s2[sd.y] + 1e-16f);
    atomicAdd(&g_out2[sd.y * NCLS + c], g_H2[sd.x * NCLS + c] * w);
}

__global__ void k_final(float* __restrict__ out, const float* __restrict__ b2) {
    int d = blockIdx.x;
    int lane = threadIdx.x;
    float v0 = (lane < NCLS) ? g_out2[d * NCLS + lane] + b2[lane] : -INFINITY;
    float v1 = (lane + 32 < NCLS) ? g_out2[d * NCLS + lane + 32] + b2[lane + 32] : -INFINITY;
    float m = fmaxf(v0, v1);
#pragma unroll
    for (int o = 16; o > 0; o >>= 1) m = fmaxf(m, __shfl_xor_sync(0xffffffffu, m, o));
    float s = ((lane < NCLS) ? expf(v0 - m) : 0.f) + ((lane + 32 < NCLS) ? expf(v1 - m) : 0.f);
#pragma unroll
    for (int o = 16; o > 0; o >>= 1) s += __shfl_xor_sync(0xffffffffu, s, o);
    float ls = m + logf(s);
    if (lane < NCLS) out[d * NCLS + lane] = v0 - ls;
    if (lane + 32 < NCLS) out[d * NCLS + lane + 32] = v1 - ls;
}

// ---------------- launch ----------------
extern "C" void kernel_launch(void* const* d_in, const int* in_sizes, int n_in,
                              void* d_out, int out_size) {
    const float* x = nullptr;
    const void* e1 = nullptr;
    const void* e2 = nullptr;
    const float *W1 = nullptr, *as1 = nullptr, *ad1 = nullptr, *b1 = nullptr;
    const float *W2 = nullptr, *as2 = nullptr, *ad2 = nullptr, *b2 = nullptr;

    for (int i = 0; i < n_in; i++) {
        switch (in_sizes[i]) {
            case N0 * F_IN:   x  = (const float*)d_in[i]; break;
            case 2 * E1N:     e1 = d_in[i]; break;
            case 2 * E2N:     e2 = d_in[i]; break;
            case F_IN * D1:
                W1  = (const float*)d_in[i];
                if (i + 3 < n_in) {
                    as1 = (const float*)d_in[i + 1];
                    ad1 = (const float*)d_in[i + 2];
                    b1  = (const float*)d_in[i + 3];
                }
                break;
            case D1 * NCLS:
                W2  = (const float*)d_in[i];
                if (i + 3 < n_in) {
                    as2 = (const float*)d_in[i + 1];
                    ad2 = (const float*)d_in[i + 2];
                    b2  = (const float*)d_in[i + 3];
                }
                break;
            default: break;
        }
    }

    float* out = (float*)d_out;
    const int TPB = 256;

    cudaFuncSetAttribute(k_gemm1_mma, cudaFuncAttributeMaxDynamicSharedMemorySize, SMEM_G1);

    k_prep<<<512, TPB>>>(W1, e1, e2);
    k_count<<<(EL1 + TPB - 1) / TPB, TPB>>>();
    k_scan<<<1, 1024>>>();
    k_scatter<<<(EL1 + TPB - 1) / TPB, TPB>>>();
    k_gemm1_mma<<<(N0 + 127) / 128, TPB, SMEM_G1>>>(x, as1, ad1);
    k_edge1_fused<<<(N1V * 32 + TPB - 1) / TPB, TPB>>>(b1);
    k_gemm2<<<(N1V * NCLS + TPB - 1) / TPB, TPB>>>(W2);
    k_att2<<<(N1V + TPB - 1) / TPB, TPB>>>(as2, ad2);
    k_edge2_sum<<<(EL2 + TPB - 1) / TPB, TPB>>>();
    k_edge2_agg<<<(EL2 * NCLS + TPB - 1) / TPB, TPB>>>();
    k_final<<<N2V, 32>>>(out, b2);
}

// round 7
// speedup vs baseline: 2.3394x; 1.1393x over previous
#include <cuda_runtime.h>
#include <cuda_bf16.h>
#include <math.h>

#define N0   120000
#define N1V  12000
#define N2V  1024
#define E1N  300000
#define E2N  10240
#define F_IN 602
#define H1N  8
#define C1N  8
#define D1   64
#define NCLS 41
#define NEG  0.2f

#define EL1  (E1N + N1V)   // 312000
#define EL2  (E2N + N2V)   // 11264
#define KPAD 608
#define CAP  128           // bucket capacity per dst node (Poisson(25) tail ~1e-45)

// ---------------- scratch ----------------
__device__ float          g_Hfull[(size_t)N0 * D1];
__device__ float          g_as1[N0 * H1N];
__device__ float          g_ad1[N1V * H1N];
__device__ float          g_ex1[(size_t)N1V * CAP * H1N];
__device__ float          g_out1[N1V * D1];
__device__ float          g_H2[N1V * NCLS];
__device__ float          g_as2[N1V];
__device__ float          g_ad2[N2V];
__device__ float          g_s2[N2V];
__device__ float          g_out2[N2V * NCLS];
__device__ __nv_bfloat16  g_W1h[D1 * KPAD];
__device__ __nv_bfloat16  g_W1l[D1 * KPAD];
__device__ int2           g_e2sd[EL2];
__device__ int            g_cnt1[N1V];
__device__ int            g_nbr1[N1V * CAP];

// ================= zero counters / accumulators =================
__global__ void k_zero() {
    int i = blockIdx.x * blockDim.x + threadIdx.x;
    if (i < N1V) g_cnt1[i] = 0;
    if (i < N2V * NCLS) g_out2[i] = 0.f;
    if (i < N2V) g_s2[i] = 0.f;
}

// ================= prep: W1 split + edge decode + bucket scatter =================
__global__ void k_prep(const float* __restrict__ W1, const void* e1, const void* e2) {
    __shared__ int se64;
    if (threadIdx.x == 0) {
        const long long* p = (const long long*)e1;
        bool ok = true;
        for (int i = 0; i < 16; i++) {
            long long v = p[i];
            if (v < 0 || v >= (long long)N0) { ok = false; break; }
        }
        se64 = ok ? 1 : 0;
    }
    __syncthreads();
    int e64 = se64;
    int nt = gridDim.x * blockDim.x;
    int t0 = blockIdx.x * blockDim.x + threadIdx.x;

    for (int i = t0; i < D1 * KPAD; i += nt) {
        int n = i / KPAD, k = i - n * KPAD;
        float v = (k < F_IN) ? W1[(size_t)k * D1 + n] : 0.f;
        __nv_bfloat16 h = __float2bfloat16(v);
        g_W1h[i] = h;
        g_W1l[i] = __float2bfloat16(v - __bfloat162float(h));
    }
    // layer-1 edges: decode + scatter into per-dst buckets (incl. self loops)
    for (int e = t0; e < EL1; e += nt) {
        int s, d;
        if (e < E1N) {
            if (e64) {
                s = (int)((const long long*)e1)[e];
                d = (int)((const long long*)e1)[E1N + e];
            } else {
                s = ((const int*)e1)[e];
                d = ((const int*)e1)[E1N + e];
            }
        } else { s = d = e - E1N; }
        int pos = atomicAdd(&g_cnt1[d], 1);
        if (pos < CAP) g_nbr1[d * CAP + pos] = s;
    }
    for (int e = t0; e < EL2; e += nt) {
        int s, d;
        if (e < E2N) {
            if (e64) {
                s = (int)((const long long*)e2)[e];
                d = (int)((const long long*)e2)[E2N + e];
            } else {
                s = ((const int*)e2)[e];
                d = ((const int*)e2)[E2N + e];
            }
        } else { s = d = e - E2N; }
        g_e2sd[e] = make_int2(s, d);
    }
}

// ================= GEMM1: mma.sync bf16x3, ldmatrix, cp.async B =================
#define KC      32
#define NCHUNK  19
#define SA_U32  20
#define SRB     80
#define OFF_AH  0
#define OFF_AL  10240
#define OFF_BH  20480
#define OFF_BL  25600
#define BUFB    30720
#define SMEM_G1 (2 * BUFB)
#define CS_STRIDE 72

__device__ __forceinline__ unsigned smem_u32(const void* p) {
    unsigned a;
    asm("{ .reg .u64 t; cvta.to.shared.u64 t, %1; cvt.u32.u64 %0, t; }" : "=r"(a) : "l"(p));
    return a;
}

__device__ __forceinline__ void cvt2(float2 v, unsigned& hp, unsigned& lp) {
    __nv_bfloat16 hx = __float2bfloat16(v.x), hy = __float2bfloat16(v.y);
    float rx = v.x - __bfloat162float(hx), ry = v.y - __bfloat162float(hy);
    __nv_bfloat16 lx = __float2bfloat16(rx), ly = __float2bfloat16(ry);
    hp = ((unsigned)__bfloat16_as_ushort(hy) << 16) | __bfloat16_as_ushort(hx);
    lp = ((unsigned)__bfloat16_as_ushort(ly) << 16) | __bfloat16_as_ushort(lx);
}

__device__ __forceinline__ void mma_bf16(float* c, const unsigned* a, unsigned b0, unsigned b1) {
    asm volatile(
        "mma.sync.aligned.m16n8k16.row.col.f32.bf16.bf16.f32 "
        "{%0,%1,%2,%3}, {%4,%5,%6,%7}, {%8,%9}, {%0,%1,%2,%3};"
        : "+f"(c[0]), "+f"(c[1]), "+f"(c[2]), "+f"(c[3])
        : "r"(a[0]), "r"(a[1]), "r"(a[2]), "r"(a[3]), "r"(b0), "r"(b1));
}

__device__ __forceinline__ void ldm4(unsigned addr, unsigned* r) {
    asm volatile("ldmatrix.sync.aligned.m8n8.x4.shared.b16 {%0,%1,%2,%3}, [%4];"
                 : "=r"(r[0]), "=r"(r[1]), "=r"(r[2]), "=r"(r[3]) : "r"(addr));
}

__device__ __forceinline__ void cpa16(unsigned dst, const void* src) {
    asm volatile("cp.async.cg.shared.global [%0], [%1], 16;" :: "r"(dst), "l"(src));
}

__global__ void __launch_bounds__(256, 2)
k_gemm1_mma(const float* __restrict__ x,
            const float* __restrict__ a_src, const float* __restrict__ a_dst) {
    extern __shared__ unsigned char smem[];
    unsigned sb = smem_u32(smem);
    int t = threadIdx.x;
    int w = t >> 5, lane = t & 31;
    int g = lane >> 2, tig = lane & 3;
    int wm = w & 3, wn = w >> 2;
    int row0 = blockIdx.x * 128;

    float acc[2][4][4];
#pragma unroll
    for (int mi = 0; mi < 2; mi++)
#pragma unroll
        for (int ni = 0; ni < 4; ni++)
#pragma unroll
            for (int q = 0; q < 4; q++) acc[mi][ni][q] = 0.f;

    int bn = t >> 2, bq = t & 3;
    unsigned bdst_off = bn * SRB + bq * 16;
    int bsrc_elem = bn * KPAD + bq * 8;

    int arow = ((lane >> 3) & 1) * 8 + (lane & 7);
    unsigned a_loff = (unsigned)((wm * 32 + arow) * SRB + (lane >> 4) * 16);
    int brow = ((lane >> 4) << 3) + (lane & 7);
    unsigned b_loff = (unsigned)((wn * 32 + brow) * SRB + ((lane >> 3) & 1) * 16);

    {
        unsigned* Ah = (unsigned*)(smem + OFF_AH);
        unsigned* Al = (unsigned*)(smem + OFF_AL);
#pragma unroll
        for (int j = 0; j < 8; j++) {
            int idx = t + 256 * j;
            int row = idx >> 4, kq = idx & 15;
            float2 v = make_float2(0.f, 0.f);
            if (row0 + row < N0)
                v = *(const float2*)(x + (size_t)(row0 + row) * F_IN + 2 * kq);
            unsigned hp, lp; cvt2(v, hp, lp);
            Ah[row * SA_U32 + kq] = hp; Al[row * SA_U32 + kq] = lp;
        }
        cpa16(sb + OFF_BH + bdst_off, (const void*)(g_W1h + bsrc_elem));
        cpa16(sb + OFF_BL + bdst_off, (const void*)(g_W1l + bsrc_elem));
        asm volatile("cp.async.commit_group;");
        asm volatile("cp.async.wait_group 0;");
    }
    __syncthreads();

    for (int c = 0; c < NCHUNK; c++) {
        int cur = c & 1, nxt = cur ^ 1;
        bool have_next = (c + 1 < NCHUNK);
        float2 av[8];
        if (have_next) {
            int k0 = (c + 1) * KC;
            int ksrc = bsrc_elem + k0;
            cpa16(sb + nxt * BUFB + OFF_BH + bdst_off, (const void*)(g_W1h + ksrc));
            cpa16(sb + nxt * BUFB + OFF_BL + bdst_off, (const void*)(g_W1l + ksrc));
            asm volatile("cp.async.commit_group;");
#pragma unroll
            for (int j = 0; j < 8; j++) {
                int idx = t + 256 * j;
                int row = idx >> 4, kq = idx & 15;
                int gk = k0 + 2 * kq;
                float2 v = make_float2(0.f, 0.f);
                if (row0 + row < N0 && gk < F_IN)
                    v = *(const float2*)(x + (size_t)(row0 + row) * F_IN + gk);
                av[j] = v;
            }
        }
        {
            unsigned abh = sb + cur * BUFB + OFF_AH + a_loff;
            unsigned abl = sb + cur * BUFB + OFF_AL + a_loff;
            unsigned bbh = sb + cur * BUFB + OFF_BH + b_loff;
            unsigned bbl = sb + cur * BUFB + OFF_BL + b_loff;
#pragma unroll
            for (int kb = 0; kb < 2; kb++) {
                unsigned ko = kb * 32;
                unsigned ah[2][4], al[2][4], bh[2][4], bl[2][4];
#pragma unroll
                for (int mi = 0; mi < 2; mi++) {
                    ldm4(abh + mi * (16 * SRB) + ko, ah[mi]);
                    ldm4(abl + mi * (16 * SRB) + ko, al[mi]);
                }
#pragma unroll
                for (int nb = 0; nb < 2; nb++) {
                    ldm4(bbh + nb * (16 * SRB) + ko, bh[nb]);
                    ldm4(bbl + nb * (16 * SRB) + ko, bl[nb]);
                }
#pragma unroll
                for (int mi = 0; mi < 2; mi++)
#pragma unroll
                    for (int nb = 0; nb < 2; nb++) {
                        mma_bf16(acc[mi][nb * 2 + 0], ah[mi], bh[nb][0], bh[nb][1]);
                        mma_bf16(acc[mi][nb * 2 + 1], ah[mi], bh[nb][2], bh[nb][3]);
                        mma_bf16(acc[mi][nb * 2 + 0], al[mi], bh[nb][0], bh[nb][1]);
                        mma_bf16(acc[mi][nb * 2 + 1], al[mi], bh[nb][2], bh[nb][3]);
                        mma_bf16(acc[mi][nb * 2 + 0], ah[mi], bl[nb][0], bl[nb][1]);
                        mma_bf16(acc[mi][nb * 2 + 1], ah[mi], bl[nb][2], bl[nb][3]);
                    }
            }
        }
        if (have_next) {
            unsigned* Ah = (unsigned*)(smem + nxt * BUFB + OFF_AH);
            unsigned* Al = (unsigned*)(smem + nxt * BUFB + OFF_AL);
#pragma unroll
            for (int j = 0; j < 8; j++) {
                int idx = t + 256 * j;
                int row = idx >> 4, kq = idx & 15;
                unsigned hp, lp; cvt2(av[j], hp, lp);
                Ah[row * SA_U32 + kq] = hp; Al[row * SA_U32 + kq] = lp;
            }
        }
        asm volatile("cp.async.wait_group 0;");
        __syncthreads();
    }

    float* Cs = (float*)smem;
#pragma unroll
    for (int mi = 0; mi < 2; mi++)
#pragma unroll
        for (int ni = 0; ni < 4; ni++) {
            int r = wm * 32 + mi * 16 + g;
            int cc = wn * 32 + ni * 8 + tig * 2;
            Cs[r * CS_STRIDE + cc]           = acc[mi][ni][0];
            Cs[r * CS_STRIDE + cc + 1]       = acc[mi][ni][1];
            Cs[(r + 8) * CS_STRIDE + cc]     = acc[mi][ni][2];
            Cs[(r + 8) * CS_STRIDE + cc + 1] = acc[mi][ni][3];
        }
    __syncthreads();

#pragma unroll
    for (int it = 0; it < 8; it++) {
        int r = (t >> 4) + 16 * it;
        int c4 = (t & 15) * 4;
        if (row0 + r < N0) {
            float4 v = *(const float4*)(Cs + r * CS_STRIDE + c4);
            *(float4*)(g_Hfull + (size_t)(row0 + r) * D1 + c4) = v;
        }
    }
    if (t < 128) {
        int m = row0 + t;
        if (m < N0) {
            const float* rr = Cs + t * CS_STRIDE;
#pragma unroll
            for (int h = 0; h < H1N; h++) {
                float as = 0.f, ad = 0.f;
#pragma unroll
                for (int cc = 0; cc < C1N; cc++) {
                    float v = rr[h * C1N + cc];
                    as = fmaf(v, __ldg(&a_src[h * C1N + cc]), as);
                    ad = fmaf(v, __ldg(&a_dst[h * C1N + cc]), ad);
                }
                g_as1[m * H1N + h] = as;
                if (m < N1V) g_ad1[m * H1N + h] = ad;
            }
        }
    }
}

// ================= fused layer-1 softmax + aggregate + bias + ELU (warp per dst) =================
__global__ void __launch_bounds__(256)
k_edge1_fused(const float* __restrict__ b1) {
    int node = (blockIdx.x * blockDim.x + threadIdx.x) >> 5;
    int lane = threadIdx.x & 31;
    if (node >= N1V) return;
    int deg = g_cnt1[node];
    if (deg > CAP) deg = CAP;
    const int* nbr = g_nbr1 + node * CAP;
    float* exb = g_ex1 + (size_t)node * CAP * 8;

    float4 adA = __ldg((const float4*)&g_ad1[node * 8]);
    float4 adB = __ldg((const float4*)&g_ad1[node * 8 + 4]);
    float sum[8] = {0.f, 0.f, 0.f, 0.f, 0.f, 0.f, 0.f, 0.f};

    for (int e = lane; e < deg; e += 32) {
        int s = __ldg(&nbr[e]);
        float4 sa = __ldg((const float4*)&g_as1[s * 8]);
        float4 sbv = __ldg((const float4*)&g_as1[s * 8 + 4]);
        float a[8] = { sa.x + adA.x, sa.y + adA.y, sa.z + adA.z, sa.w + adA.w,
                       sbv.x + adB.x, sbv.y + adB.y, sbv.z + adB.z, sbv.w + adB.w };
        float ex[8];
#pragma unroll
        for (int h = 0; h < 8; h++) {
            float v = a[h] > 0.f ? a[h] : NEG * a[h];
            ex[h] = expf(v);
            sum[h] += ex[h];
        }
        *(float4*)&exb[(size_t)e * 8]     = make_float4(ex[0], ex[1], ex[2], ex[3]);
        *(float4*)&exb[(size_t)e * 8 + 4] = make_float4(ex[4], ex[5], ex[6], ex[7]);
    }
#pragma unroll
    for (int h = 0; h < 8; h++)
#pragma unroll
        for (int o = 16; o > 0; o >>= 1)
            sum[h] += __shfl_xor_sync(0xffffffffu, sum[h], o);

    int myh = lane >> 2;
    float myr = 1.f / (sum[myh] + 1e-16f);

    float ax = 0.f, ay = 0.f;
    for (int e = 0; e < deg; e++) {
        int s = __ldg(&nbr[e]);
        float wgt = __ldg(&exb[(size_t)e * 8 + myh]) * myr;
        float2 hv = __ldg((const float2*)&g_Hfull[(size_t)s * D1 + 2 * lane]);
        ax = fmaf(wgt, hv.x, ax);
        ay = fmaf(wgt, hv.y, ay);
    }
    float bx = __ldg(&b1[2 * lane]), by = __ldg(&b1[2 * lane + 1]);
    float vx = ax + bx; vx = vx > 0.f ? vx : expm1f(vx);
    float vy = ay + by; vy = vy > 0.f ? vy : expm1f(vy);
    *(float2*)&g_out1[node * D1 + 2 * lane] = make_float2(vx, vy);
}

// ================= layer 2 =================
__global__ void k_gemm2(const float* __restrict__ W2) {
    __shared__ float Ws[D1 * NCLS];
    for (int i = threadIdx.x; i < D1 * NCLS; i += blockDim.x) Ws[i] = W2[i];
    __syncthreads();
    int t = blockIdx.x * blockDim.x + threadIdx.x;
    if (t >= N1V * NCLS) return;
    int row = t / NCLS, col = t - row * NCLS;
    const float* hr = g_out1 + row * D1;
    float acc = 0.f;
#pragma unroll
    for (int k = 0; k < D1; k++) acc = fmaf(hr[k], Ws[k * NCLS + col], acc);
    g_H2[t] = acc;
}

__global__ void k_att2(const float* __restrict__ a_src, const float* __restrict__ a_dst) {
    int i = blockIdx.x * blockDim.x + threadIdx.x;
    if (i >= N1V) return;
    const float* hp = g_H2 + i * NCLS;
    float as = 0.f;
#pragma unroll
    for (int c = 0; c < NCLS; c++) as += hp[c] * a_src[c];
    g_as2[i] = as;
    if (i < N2V) {
        float ad = 0.f;
#pragma unroll
        for (int c = 0; c < NCLS; c++) ad += hp[c] * a_dst[c];
        g_ad2[i] = ad;
    }
}

__global__ void k_edge2_sum() {
    int e = blockIdx.x * blockDim.x + threadIdx.x;
    if (e >= EL2) return;
    int2 sd = g_e2sd[e];
    float al = g_as2[sd.x] + g_ad2[sd.y];
    al = al > 0.f ? al : NEG * al;
    atomicAdd(&g_s2[sd.y], expf(al));
}

__global__ void k_edge2_agg() {
    int t = blockIdx.x * blockDim.x + threadIdx.x;
    if (t >= EL2 * NCLS) return;
    int e = t / NCLS, c = t - e * NCLS;
    int2 sd = g_e2sd[e];
    float al = g_as2[sd.x] + g_ad2[sd.y];
    al = al > 0.f ? al : NEG * al;
    float w = expf(al) / (g_s2[sd.y] + 1e-16f);
    atomicAdd(&g_out2[sd.y * NCLS + c], g_H2[sd.x * NCLS + c] * w);
}

__global__ void k_final(float* __restrict__ out, const float* __restrict__ b2) {
    int d = blockIdx.x;
    int lane = threadIdx.x;
    float v0 = (lane < NCLS) ? g_out2[d * NCLS + lane] + b2[lane] : -INFINITY;
    float v1 = (lane + 32 < NCLS) ? g_out2[d * NCLS + lane + 32] + b2[lane + 32] : -INFINITY;
    float m = fmaxf(v0, v1);
#pragma unroll
    for (int o = 16; o > 0; o >>= 1) m = fmaxf(m, __shfl_xor_sync(0xffffffffu, m, o));
    float s = ((lane < NCLS) ? expf(v0 - m) : 0.f) + ((lane + 32 < NCLS) ? expf(v1 - m) : 0.f);
#pragma unroll
    for (int o = 16; o > 0; o >>= 1) s += __shfl_xor_sync(0xffffffffu, s, o);
    float ls = m + logf(s);
    if (lane < NCLS) out[d * NCLS + lane] = v0 - ls;
    if (lane + 32 < NCLS) out[d * NCLS + lane + 32] = v1 - ls;
}

// ---------------- launch ----------------
extern "C" void kernel_launch(void* const* d_in, const int* in_sizes, int n_in,
                              void* d_out, int out_size) {
    const float* x = nullptr;
    const void* e1 = nullptr;
    const void* e2 = nullptr;
    const float *W1 = nullptr, *as1 = nullptr, *ad1 = nullptr, *b1 = nullptr;
    const float *W2 = nullptr, *as2 = nullptr, *ad2 = nullptr, *b2 = nullptr;

    for (int i = 0; i < n_in; i++) {
        switch (in_sizes[i]) {
            case N0 * F_IN:   x  = (const float*)d_in[i]; break;
            case 2 * E1N:     e1 = d_in[i]; break;
            case 2 * E2N:     e2 = d_in[i]; break;
            case F_IN * D1:
                W1  = (const float*)d_in[i];
                if (i + 3 < n_in) {
                    as1 = (const float*)d_in[i + 1];
                    ad1 = (const float*)d_in[i + 2];
                    b1  = (const float*)d_in[i + 3];
                }
                break;
            case D1 * NCLS:
                W2  = (const float*)d_in[i];
                if (i + 3 < n_in) {
                    as2 = (const float*)d_in[i + 1];
                    ad2 = (const float*)d_in[i + 2];
                    b2  = (const float*)d_in[i + 3];
                }
                break;
            default: break;
        }
    }

    float* out = (float*)d_out;
    const int TPB = 256;

    cudaFuncSetAttribute(k_gemm1_mma, cudaFuncAttributeMaxDynamicSharedMemorySize, SMEM_G1);

    k_zero<<<(N2V * NCLS + TPB - 1) / TPB, TPB>>>();
    k_prep<<<512, TPB>>>(W1, e1, e2);
    k_gemm1_mma<<<(N0 + 127) / 128, TPB, SMEM_G1>>>(x, as1, ad1);
    k_edge1_fused<<<(N1V * 32 + TPB - 1) / TPB, TPB>>>(b1);
    k_gemm2<<<(N1V * NCLS + TPB - 1) / TPB, TPB>>>(W2);
    k_att2<<<(N1V + TPB - 1) / TPB, TPB>>>(as2, ad2);
    k_edge2_sum<<<(EL2 + TPB - 1) / TPB, TPB>>>();
    k_edge2_agg<<<(EL2 * NCLS + TPB - 1) / TPB, TPB>>>();
    k_final<<<N2V, 32>>>(out, b2);
}